// round 6
// baseline (speedup 1.0000x reference)
#include <cuda_runtime.h>
#include <math.h>
#include <stdint.h>

#define TT 32
#define NN 256
#define LL 512
#define HH 128
#define G3 384
#define NA 16
#define TOTP 277
#define XP 130   // float2 pitch for duplicated X tile
#define WP 132   // float pitch for W tile

typedef unsigned long long u64;

__device__ __forceinline__ u64 ff2(u64 a, u64 b, u64 c) {
    u64 d;
    asm("fma.rn.f32x2 %0, %1, %2, %3;" : "=l"(d) : "l"(a), "l"(b), "l"(c));
    return d;
}
__device__ __forceinline__ float2 unpack(u64 v) {
    float2 r;
    asm("mov.b64 {%0,%1}, %2;" : "=f"(r.x), "=f"(r.y) : "l"(v));
    return r;
}

__device__ float g_X[LL*NN*HH];     // conv out / layer outputs
__device__ float g_gi[LL*NN*G3];    // precomputed input-gates
__device__ float g_G[TT*NN*HH];     // gathered rows, then H0 series
__device__ float g_H1[TT*NN*HH];    // H1 series
__device__ float g_gum[TT*NN*NA];   // gumbel noise

// ---------------------------------------------------------------- conv
__global__ void conv_k(const float* __restrict__ obs, const float* __restrict__ cw,
                       const float* __restrict__ cb) {
    int l = blockIdx.x, n = blockIdx.y, h = threadIdx.x;
    __shared__ float xs[9];
    if (h < 9) { int p = l - 4 + h; xs[h] = (p >= 0 && p < LL) ? obs[n*LL + p] : 0.f; }
    __syncthreads();
    float acc = cb[h];
#pragma unroll
    for (int k = 0; k < 9; k++) acc = fmaf(xs[k], cw[h*9 + k], acc);
    g_X[(l*NN + n)*HH + h] = fmaxf(acc, 0.f);
}

// ------------------------------------------------ GEMM: C[r][g] = bias[g] + X[r]·W[g]
// X [R,128] row-major, W [384,128] row-major, C [R,384]. 128x128 tile, 512 thr,
// 4x8 micro-tile, f32x2 packed FMA, duplicated-X smem tile (no pack MOVs).
__global__ void __launch_bounds__(512, 1)
gemm3_k(const float* __restrict__ X, const float* __restrict__ W,
        const float* __restrict__ bias, float* __restrict__ C) {
    extern __shared__ float sm[];
    float2* Xs = (float2*)sm;              // [128][XP] duplicated (x,x)
    float*  Ws = sm + 2*128*XP;            // [128][WP]
    int tid = threadIdx.x;
    int r0 = blockIdx.x * 128, g0 = blockIdx.y * 128;
    // X tile: coalesced float4 global loads, transposed dup stores
#pragma unroll
    for (int it = 0; it < 8; it++) {
        int idx = it * 512 + tid;
        int r = idx >> 5, kq = (idx & 31) * 4;
        float4 v = *(const float4*)&X[(size_t)(r0 + r) * HH + kq];
        Xs[(kq+0)*XP + r] = make_float2(v.x, v.x);
        Xs[(kq+1)*XP + r] = make_float2(v.y, v.y);
        Xs[(kq+2)*XP + r] = make_float2(v.z, v.z);
        Xs[(kq+3)*XP + r] = make_float2(v.w, v.w);
    }
    // W tile
#pragma unroll
    for (int it = 0; it < 8; it++) {
        int idx = it * 512 + tid;
        int g = idx & 127, kq = (idx >> 7) * 4;
        float4 w = *(const float4*)&W[(size_t)(g0 + g) * HH + kq];
        Ws[(kq+0)*WP + g] = w.x;
        Ws[(kq+1)*WP + g] = w.y;
        Ws[(kq+2)*WP + g] = w.z;
        Ws[(kq+3)*WP + g] = w.w;
    }
    __syncthreads();
    int tx = tid & 15, ty = tid >> 4;   // tx: 8-col group (16), ty: 4-row group (32)
    u64 acc[4][4];
#pragma unroll
    for (int i = 0; i < 4; i++)
#pragma unroll
        for (int j = 0; j < 4; j++) acc[i][j] = 0ULL;
#pragma unroll 8
    for (int k = 0; k < 128; k++) {
        const float2* xk = Xs + k * XP + ty * 4;
        const float*  wk = Ws + k * WP + tx * 8;
        ulonglong2 a01 = *(const ulonglong2*)(xk);
        ulonglong2 a23 = *(const ulonglong2*)(xk + 2);
        ulonglong2 b01 = *(const ulonglong2*)(wk);
        ulonglong2 b23 = *(const ulonglong2*)(wk + 4);
        u64 av[4] = {a01.x, a01.y, a23.x, a23.y};
        u64 bv[4] = {b01.x, b01.y, b23.x, b23.y};
#pragma unroll
        for (int i = 0; i < 4; i++)
#pragma unroll
            for (int j = 0; j < 4; j++)
                acc[i][j] = ff2(av[i], bv[j], acc[i][j]);
    }
    float4 bA = *(const float4*)&bias[g0 + tx*8];
    float4 bB = *(const float4*)&bias[g0 + tx*8 + 4];
#pragma unroll
    for (int i = 0; i < 4; i++) {
        int r = r0 + ty*4 + i;
        float2 q0 = unpack(acc[i][0]), q1 = unpack(acc[i][1]);
        float2 q2 = unpack(acc[i][2]), q3 = unpack(acc[i][3]);
        float4 o0 = make_float4(q0.x + bA.x, q0.y + bA.y, q1.x + bA.z, q1.y + bA.w);
        float4 o1 = make_float4(q2.x + bB.x, q2.y + bB.y, q3.x + bB.z, q3.y + bB.w);
        *(float4*)&C[(size_t)r * G3 + g0 + tx*8]     = o0;
        *(float4*)&C[(size_t)r * G3 + g0 + tx*8 + 4] = o1;
    }
}

// ---------------------------------------------- GRU recurrence, one layer
// 128 CTAs x 2 samples, 384 threads. W_hh k=0..95 in registers (48 u64 pairs),
// k=96..127 in smem. k-paired f32x2 FMA. gi precomputed (incl. bih).
__global__ void __launch_bounds__(384, 1)
recur2_k(const float* __restrict__ gi, const float* __restrict__ whh,
         const float* __restrict__ bhh, const float* __restrict__ h0i,
         float* __restrict__ out, int steps) {
    extern __shared__ float sm[];
    float* Wsm = sm;                 // [384][36] k=96..127 (pitch 36, conflict-free)
    float* h_s = Wsm + 384*36;       // [2][128]
    float* su  = h_s + 256;          // [2][384]
    float* gin = su + 768;           // [2][128]
    int g = threadIdx.x;
    int n0 = blockIdx.x * 2;
    u64 wr[48];
#pragma unroll
    for (int i = 0; i < 24; i++) {
        ulonglong2 t = *(const ulonglong2*)&whh[(size_t)g * HH + 4*i];
        wr[2*i] = t.x; wr[2*i+1] = t.y;
    }
#pragma unroll
    for (int j = 0; j < 8; j++)
        *(float4*)&Wsm[g*36 + 4*j] = *(const float4*)&whh[(size_t)g * HH + 96 + 4*j];
    float bv = bhh[g];
    if (g < 256) {
        int s = g >> 7, j = g & 127;
        h_s[g] = h0i ? h0i[(size_t)(n0 + s) * HH + j] : 0.f;
    }
    __syncthreads();
    const ulonglong2* h0p = (const ulonglong2*)h_s;
    const ulonglong2* h1p = (const ulonglong2*)(h_s + HH);
    const ulonglong2* wsp = (const ulonglong2*)&Wsm[g*36];
    for (int t = 0; t < steps; t++) {
        const float* gp = gi + (size_t)t * NN * G3;
        float gia = gp[n0 * G3 + g];
        float gib = gp[(n0 + 1) * G3 + g];
        u64 a0a = 0, a0b = 0, a1a = 0, a1b = 0;
#pragma unroll
        for (int i = 0; i < 24; i++) {
            ulonglong2 ha = h0p[i], hb = h1p[i];
            a0a = ff2(wr[2*i],   ha.x, a0a);
            a0b = ff2(wr[2*i+1], ha.y, a0b);
            a1a = ff2(wr[2*i],   hb.x, a1a);
            a1b = ff2(wr[2*i+1], hb.y, a1b);
        }
#pragma unroll
        for (int i = 0; i < 8; i++) {
            ulonglong2 ww = wsp[i];
            ulonglong2 ha = h0p[24+i], hb = h1p[24+i];
            a0a = ff2(ww.x, ha.x, a0a);
            a0b = ff2(ww.y, ha.y, a0b);
            a1a = ff2(ww.x, hb.x, a1a);
            a1b = ff2(ww.y, hb.y, a1b);
        }
        float2 s0a = unpack(a0a), s0b = unpack(a0b);
        float2 s1a = unpack(a1a), s1b = unpack(a1b);
        float a0 = bv + ((s0a.x + s0a.y) + (s0b.x + s0b.y));
        float a1 = bv + ((s1a.x + s1a.y) + (s1b.x + s1b.y));
        if (g < 256) { su[g] = gia + a0; su[G3 + g] = gib + a1; }
        else { su[g] = a0; su[G3 + g] = a1; gin[g - 256] = gia; gin[HH + g - 256] = gib; }
        __syncthreads();
        if (g < 256) {
            int s = g >> 7, j = g & 127;
            const float* ss = su + s * G3;
            float r = 1.f / (1.f + __expf(-ss[j]));
            float z = 1.f / (1.f + __expf(-ss[128 + j]));
            float y = fmaf(r, ss[256 + j], gin[s * HH + j]);
            float e = __expf(-2.f * fabsf(y));
            float th = (1.f - e) / (1.f + e);
            th = (y < 0.f) ? -th : th;
            float hn = (1.f - z) * th + z * h_s[g];
            h_s[g] = hn;
            out[((size_t)t * NN + n0 + s) * HH + j] = hn;
        }
        __syncthreads();
    }
}

// ---------------------------------------------------------------- gather M[n, p0+t]
__global__ void gather_k(const int* __restrict__ p0) {
    int t = blockIdx.x, n = blockIdx.y, h = threadIdx.x;
    int p = p0[n] + t;
    g_G[((size_t)t * NN + n) * HH + h] = g_X[((size_t)p * NN + n) * HH + h];
}

// ---------------------------------------------------------------- threefry gumbel
// JAX partitionable threefry: bits[i] = o0 ^ o1, counter (0, i), key (0, 42).
__device__ __forceinline__ uint32_t rotl32(uint32_t x, int r) { return (x << r) | (x >> (32 - r)); }
__device__ __forceinline__ float bits_to_gumbel(uint32_t b) {
    uint32_t fb = (b >> 9) | 0x3f800000u;
    float f = __uint_as_float(fb) - 1.0f;
    float u = (f > 0.f) ? f : 1.17549435e-38f;
    return -logf(-logf(u));
}
__global__ void gumbel_k() {
    int i = blockIdx.x * blockDim.x + threadIdx.x;
    if (i >= TT*NN*NA) return;
    const uint32_t ks0 = 0u, ks1 = 42u, ks2 = ks0 ^ ks1 ^ 0x1BD11BDAu;
    uint32_t x0 = 0u + ks0, x1 = (uint32_t)i + ks1;
#define RG4(a,b,c,d) \
    x0 += x1; x1 = rotl32(x1,a); x1 ^= x0; \
    x0 += x1; x1 = rotl32(x1,b); x1 ^= x0; \
    x0 += x1; x1 = rotl32(x1,c); x1 ^= x0; \
    x0 += x1; x1 = rotl32(x1,d); x1 ^= x0;
    RG4(13,15,26,6)  x0 += ks1; x1 += ks2 + 1u;
    RG4(17,29,16,24) x0 += ks2; x1 += ks0 + 2u;
    RG4(13,15,26,6)  x0 += ks0; x1 += ks1 + 3u;
    RG4(17,29,16,24) x0 += ks1; x1 += ks2 + 4u;
    RG4(13,15,26,6)  x0 += ks2; x1 += ks0 + 5u;
#undef RG4
    g_gum[i] = bits_to_gumbel(x0 ^ x1);
}

// ---------------------------------------------------------------- heads + pack
__global__ void __launch_bounds__(64)
pack_k(const float* __restrict__ H0, const float* __restrict__ H1,
       const int* __restrict__ actions, const int* __restrict__ p0,
       const float* __restrict__ loc, const float* __restrict__ scale,
       const float* __restrict__ crw, const float* __restrict__ crb,
       const float* __restrict__ aw, const float* __restrict__ ab,
       float* __restrict__ out, int has_tail) {
    int bx = blockIdx.x;
    int t = bx >> 8, n = bx & 255;
    int tid = threadIdx.x;
    __shared__ float h1s[128];
    __shared__ float hd[17];
    const float* h1g = H1 + ((size_t)t * NN + n) * HH;
    h1s[tid] = h1g[tid]; h1s[tid + 64] = h1g[tid + 64];
    __syncthreads();
    if (tid < 17) {
        const float* w = (tid == 0) ? crw : (aw + (size_t)(tid - 1) * HH);
        float b = (tid == 0) ? crb[0] : ab[tid - 1];
        float d0 = 0, d1 = 0, d2 = 0, d3 = 0;
#pragma unroll
        for (int k = 0; k < HH; k += 4) {
            d0 = fmaf(w[k],   h1s[k],   d0); d1 = fmaf(w[k+1], h1s[k+1], d1);
            d2 = fmaf(w[k+2], h1s[k+2], d2); d3 = fmaf(w[k+3], h1s[k+3], d3);
        }
        hd[tid] = b + ((d0 + d1) + (d2 + d3));
    }
    __syncthreads();
    float* row  = out + ((size_t)t * NN + n) * TOTP;
    float* row2 = out + ((size_t)TT * NN + n) * TOTP;
    bool tail = has_tail && (t == TT - 1);
    if (tid == 0) {
        const float* lg = hd + 1;
        float m = lg[0];
#pragma unroll
        for (int a = 1; a < NA; a++) m = fmaxf(m, lg[a]);
        float ex[NA], es = 0.f;
#pragma unroll
        for (int a = 0; a < NA; a++) { ex[a] = expf(lg[a] - m); es += ex[a]; }
        float inv = 1.f / es;
        const float* gm = g_gum + ((size_t)t * NN + n) * NA;
        int best = 0; float bb = lg[0] + gm[0];
#pragma unroll
        for (int a = 1; a < NA; a++) {
            float v = lg[a] + gm[a];
            if (v > bb) { bb = v; best = a; }
        }
        int at = actions[t * NN + n];
        float av = (float)((at < 0) ? best : at);
        row[0] = av;
#pragma unroll
        for (int a = 0; a < NA; a++) row[1 + a] = ex[a] * inv;
        row[17] = loc[n]; row[18] = scale[n]; row[19] = hd[0];
        row[276] = (float)(p0[n] + t + 1);
        if (tail) {
            row2[0] = av;
            for (int a = 0; a < NA; a++) row2[1 + a] = ex[a] * inv;
            row2[17] = loc[n]; row2[18] = scale[n]; row2[19] = hd[0];
            row2[276] = row[276];
        }
    }
    const float* h0g = H0 + ((size_t)t * NN + n) * HH;
#pragma unroll
    for (int q = 0; q < 2; q++) {
        int j = tid + q * 64;
        float v0 = h0g[j], v1 = h1s[j];
        row[20 + j] = v0; row[148 + j] = v1;
        if (tail) { row2[20 + j] = v0; row2[148 + j] = v1; }
    }
}

// ---------------------------------------------------------------- launch
extern "C" void kernel_launch(void* const* d_in, const int* in_sizes, int n_in,
                              void* d_out, int out_size) {
    const float* obs    = (const float*)d_in[0];
    const int*   acts   = (const int*)d_in[1];
    const int*   p0     = (const int*)d_in[2];
    const float* h0     = (const float*)d_in[3];
    const float* loc    = (const float*)d_in[4];
    const float* scl    = (const float*)d_in[5];
    const float* conv_w = (const float*)d_in[6];
    const float* conv_b = (const float*)d_in[7];
    const float* g0wih  = (const float*)d_in[8];
    const float* g0whh  = (const float*)d_in[9];
    const float* g0bih  = (const float*)d_in[10];
    const float* g0bhh  = (const float*)d_in[11];
    const float* g1wih  = (const float*)d_in[12];
    const float* g1whh  = (const float*)d_in[13];
    const float* g1bih  = (const float*)d_in[14];
    const float* g1bhh  = (const float*)d_in[15];
    const float* crw    = (const float*)d_in[16];
    const float* crb    = (const float*)d_in[17];
    const float* aw     = (const float*)d_in[18];
    const float* ab     = (const float*)d_in[19];
    float* out = (float*)d_out;

    float *pX, *pGi, *pG, *pH1;
    cudaGetSymbolAddress((void**)&pX, g_X);
    cudaGetSymbolAddress((void**)&pGi, g_gi);
    cudaGetSymbolAddress((void**)&pG, g_G);
    cudaGetSymbolAddress((void**)&pH1, g_H1);

    const int GEMM_SMEM = (2*128*XP + 128*WP) * 4;          // 200,704 B
    const int REC_SMEM  = (384*36 + 256 + 768 + 256) * 4;   // 60,416 B
    cudaFuncSetAttribute(gemm3_k, cudaFuncAttributeMaxDynamicSharedMemorySize, GEMM_SMEM);
    cudaFuncSetAttribute(recur2_k, cudaFuncAttributeMaxDynamicSharedMemorySize, REC_SMEM);

    int has_tail = (out_size >= TT*NN*TOTP + NN*TOTP) ? 1 : 0;

    // phase 1: conv over obs[0]
    conv_k<<<dim3(LL, NN), HH>>>(obs, conv_w, conv_b);
    // phase 2: gru0 layer 0
    gemm3_k<<<dim3(LL*NN/128, 3), 512, GEMM_SMEM>>>(pX, g0wih, g0bih, pGi);
    recur2_k<<<NN/2, 384, REC_SMEM>>>(pGi, g0whh, g0bhh, nullptr, pX, LL);
    // phase 2: gru0 layer 1
    gemm3_k<<<dim3(LL*NN/128, 3), 512, GEMM_SMEM>>>(pX, g0wih + G3*HH, g0bih + G3, pGi);
    recur2_k<<<NN/2, 384, REC_SMEM>>>(pGi, g0whh + G3*HH, g0bhh + G3, nullptr, pX, LL);
    // phase 3 prep
    gather_k<<<dim3(TT, NN), HH>>>(p0);
    gumbel_k<<<512, 256>>>();
    // phase 3: layer 0
    gemm3_k<<<dim3(TT*NN/128, 3), 512, GEMM_SMEM>>>(pG, g1wih, g1bih, pGi);
    recur2_k<<<NN/2, 384, REC_SMEM>>>(pGi, g1whh, g1bhh, h0, pG, TT);          // H0 series -> g_G
    // phase 3: layer 1
    gemm3_k<<<dim3(TT*NN/128, 3), 512, GEMM_SMEM>>>(pG, g1wih + G3*HH, g1bih + G3, pGi);
    recur2_k<<<NN/2, 384, REC_SMEM>>>(pGi, g1whh + G3*HH, g1bhh + G3, h0 + NN*HH, pH1, TT);
    // heads + pack
    pack_k<<<TT*NN, 64>>>(pG, pH1, acts, p0, loc, scl, crw, crb, aw, ab, out, has_tail);
}

// round 7
// speedup vs baseline: 1.0534x; 1.0534x over previous
#include <cuda_runtime.h>
#include <math.h>
#include <stdint.h>

#define TT 32
#define NN 256
#define LL 512
#define HH 128
#define G3 384
#define NA 16
#define TOTP 277
#define GP 132   // float pitch for gemm tiles (multiple of 4 for 16B-aligned rows)

typedef unsigned long long u64;

__device__ __forceinline__ u64 ff2(u64 a, u64 b, u64 c) {
    u64 d;
    asm("fma.rn.f32x2 %0, %1, %2, %3;" : "=l"(d) : "l"(a), "l"(b), "l"(c));
    return d;
}
__device__ __forceinline__ u64 dup2(float a) {
    u64 d;
    asm("mov.b64 %0, {%1, %1};" : "=l"(d) : "f"(a));
    return d;
}
__device__ __forceinline__ float2 unpack(u64 v) {
    float2 r;
    asm("mov.b64 {%0,%1}, %2;" : "=f"(r.x), "=f"(r.y) : "l"(v));
    return r;
}

__device__ float g_X[LL*NN*HH];     // conv out / layer outputs
__device__ float g_gi[LL*NN*G3];    // precomputed input-gates
__device__ float g_G[TT*NN*HH];     // gathered rows, then H0 series
__device__ float g_H1[TT*NN*HH];    // H1 series
__device__ float g_gum[TT*NN*NA];   // gumbel noise

// ---------------------------------------------------------------- conv (grid-stride)
__global__ void conv_k(const float* __restrict__ obs, const float* __restrict__ cw,
                       const float* __restrict__ cb) {
    for (int o = blockIdx.x * blockDim.x + threadIdx.x; o < LL*NN*HH;
         o += gridDim.x * blockDim.x) {
        int h = o & 127, n = (o >> 7) & 255, l = o >> 15;
        float acc = cb[h];
#pragma unroll
        for (int k = 0; k < 9; k++) {
            int p = l - 4 + k;
            float x = (p >= 0 && p < LL) ? __ldg(&obs[n*LL + p]) : 0.f;
            acc = fmaf(x, cw[h*9 + k], acc);
        }
        g_X[o] = fmaxf(acc, 0.f);
    }
}

// ------------------------------------------------ GEMM: C[r][g] = bias[g] + X[r]·W[g]
// X [R,128] row-major, W [384,128] row-major, C [R,384]. 128x128 tile, 256 thr,
// 8x8 micro-tile, f32x2 FMA with in-register a-duplication (1.0 smem B/FMA).
__global__ void __launch_bounds__(256, 1)
gemm4_k(const float* __restrict__ X, const float* __restrict__ W,
        const float* __restrict__ bias, float* __restrict__ C) {
    extern __shared__ float sm[];
    float* Xs = sm;            // [128][GP] k-major
    float* Ws = sm + 128*GP;   // [128][GP] k-major
    int tid = threadIdx.x;
    int r0 = blockIdx.x * 128, g0 = blockIdx.y * 128;
#pragma unroll
    for (int it = 0; it < 16; it++) {
        int idx = it * 256 + tid;
        int r = idx >> 5, kq = (idx & 31) * 4;
        float4 v = *(const float4*)&X[(size_t)(r0 + r) * HH + kq];
        Xs[(kq+0)*GP + r] = v.x; Xs[(kq+1)*GP + r] = v.y;
        Xs[(kq+2)*GP + r] = v.z; Xs[(kq+3)*GP + r] = v.w;
        float4 w = *(const float4*)&W[(size_t)(g0 + r) * HH + kq];
        Ws[(kq+0)*GP + r] = w.x; Ws[(kq+1)*GP + r] = w.y;
        Ws[(kq+2)*GP + r] = w.z; Ws[(kq+3)*GP + r] = w.w;
    }
    __syncthreads();
    int tx = tid & 15, ty = tid >> 4;
    u64 acc[8][4];
#pragma unroll
    for (int i = 0; i < 8; i++)
#pragma unroll
        for (int j = 0; j < 4; j++) acc[i][j] = 0ULL;
#pragma unroll 8
    for (int k = 0; k < 128; k++) {
        const float* xk = Xs + k * GP + ty * 8;
        const float* wk = Ws + k * GP + tx * 8;
        float4 a03 = *(const float4*)(xk);
        float4 a47 = *(const float4*)(xk + 4);
        ulonglong2 b01 = *(const ulonglong2*)(wk);
        ulonglong2 b23 = *(const ulonglong2*)(wk + 4);
        u64 av[8];
        av[0] = dup2(a03.x); av[1] = dup2(a03.y);
        av[2] = dup2(a03.z); av[3] = dup2(a03.w);
        av[4] = dup2(a47.x); av[5] = dup2(a47.y);
        av[6] = dup2(a47.z); av[7] = dup2(a47.w);
        u64 bv[4] = {b01.x, b01.y, b23.x, b23.y};
#pragma unroll
        for (int i = 0; i < 8; i++)
#pragma unroll
            for (int j = 0; j < 4; j++)
                acc[i][j] = ff2(av[i], bv[j], acc[i][j]);
    }
    float4 bA = *(const float4*)&bias[g0 + tx*8];
    float4 bB = *(const float4*)&bias[g0 + tx*8 + 4];
#pragma unroll
    for (int i = 0; i < 8; i++) {
        int r = r0 + ty*8 + i;
        float2 q0 = unpack(acc[i][0]), q1 = unpack(acc[i][1]);
        float2 q2 = unpack(acc[i][2]), q3 = unpack(acc[i][3]);
        float4 o0 = make_float4(q0.x + bA.x, q0.y + bA.y, q1.x + bA.z, q1.y + bA.w);
        float4 o1 = make_float4(q2.x + bB.x, q2.y + bB.y, q3.x + bB.z, q3.y + bB.w);
        *(float4*)&C[(size_t)r * G3 + g0 + tx*8]     = o0;
        *(float4*)&C[(size_t)r * G3 + g0 + tx*8 + 4] = o1;
    }
}

// ---------------------------------------------- GRU recurrence, one layer
// 128 CTAs x 2 samples, 384 threads. W_hh k=0..95 in registers (48 u64 pairs),
// k=96..127 in smem. k-paired f32x2 FMA. gi precomputed (incl. bih).
__global__ void __launch_bounds__(384, 1)
recur2_k(const float* __restrict__ gi, const float* __restrict__ whh,
         const float* __restrict__ bhh, const float* __restrict__ h0i,
         float* __restrict__ out, int steps) {
    extern __shared__ float sm[];
    float* Wsm = sm;                 // [384][36] k=96..127 (pitch 36, conflict-free)
    float* h_s = Wsm + 384*36;       // [2][128]
    float* su  = h_s + 256;          // [2][384]
    float* gin = su + 768;           // [2][128]
    int g = threadIdx.x;
    int n0 = blockIdx.x * 2;
    u64 wr[48];
#pragma unroll
    for (int i = 0; i < 24; i++) {
        ulonglong2 t = *(const ulonglong2*)&whh[(size_t)g * HH + 4*i];
        wr[2*i] = t.x; wr[2*i+1] = t.y;
    }
#pragma unroll
    for (int j = 0; j < 8; j++)
        *(float4*)&Wsm[g*36 + 4*j] = *(const float4*)&whh[(size_t)g * HH + 96 + 4*j];
    float bv = bhh[g];
    if (g < 256) {
        int s = g >> 7, j = g & 127;
        h_s[g] = h0i ? h0i[(size_t)(n0 + s) * HH + j] : 0.f;
    }
    __syncthreads();
    const ulonglong2* h0p = (const ulonglong2*)h_s;
    const ulonglong2* h1p = (const ulonglong2*)(h_s + HH);
    const ulonglong2* wsp = (const ulonglong2*)&Wsm[g*36];
    for (int t = 0; t < steps; t++) {
        const float* gp = gi + (size_t)t * NN * G3;
        float gia = gp[n0 * G3 + g];
        float gib = gp[(n0 + 1) * G3 + g];
        u64 a0a = 0, a0b = 0, a1a = 0, a1b = 0;
#pragma unroll
        for (int i = 0; i < 24; i++) {
            ulonglong2 ha = h0p[i], hb = h1p[i];
            a0a = ff2(wr[2*i],   ha.x, a0a);
            a0b = ff2(wr[2*i+1], ha.y, a0b);
            a1a = ff2(wr[2*i],   hb.x, a1a);
            a1b = ff2(wr[2*i+1], hb.y, a1b);
        }
#pragma unroll
        for (int i = 0; i < 8; i++) {
            ulonglong2 ww = wsp[i];
            ulonglong2 ha = h0p[24+i], hb = h1p[24+i];
            a0a = ff2(ww.x, ha.x, a0a);
            a0b = ff2(ww.y, ha.y, a0b);
            a1a = ff2(ww.x, hb.x, a1a);
            a1b = ff2(ww.y, hb.y, a1b);
        }
        float2 s0a = unpack(a0a), s0b = unpack(a0b);
        float2 s1a = unpack(a1a), s1b = unpack(a1b);
        float a0 = bv + ((s0a.x + s0a.y) + (s0b.x + s0b.y));
        float a1 = bv + ((s1a.x + s1a.y) + (s1b.x + s1b.y));
        if (g < 256) { su[g] = gia + a0; su[G3 + g] = gib + a1; }
        else { su[g] = a0; su[G3 + g] = a1; gin[g - 256] = gia; gin[HH + g - 256] = gib; }
        __syncthreads();
        if (g < 256) {
            int s = g >> 7, j = g & 127;
            const float* ss = su + s * G3;
            float r = __fdividef(1.f, 1.f + __expf(-ss[j]));
            float z = __fdividef(1.f, 1.f + __expf(-ss[128 + j]));
            float y = fmaf(r, ss[256 + j], gin[s * HH + j]);
            float e = __expf(-2.f * fabsf(y));
            float th = __fdividef(1.f - e, 1.f + e);
            th = (y < 0.f) ? -th : th;
            float hn = (1.f - z) * th + z * h_s[g];
            h_s[g] = hn;
            out[((size_t)t * NN + n0 + s) * HH + j] = hn;
        }
        __syncthreads();
    }
}

// ---------------------------------------------------------------- gather M[n, p0+t]
__global__ void gather_k(const int* __restrict__ p0) {
    int t = blockIdx.x, n = blockIdx.y, h = threadIdx.x;
    int p = p0[n] + t;
    g_G[((size_t)t * NN + n) * HH + h] = g_X[((size_t)p * NN + n) * HH + h];
}

// ---------------------------------------------------------------- threefry gumbel
// JAX partitionable threefry: bits[i] = o0 ^ o1, counter (0, i), key (0, 42).
__device__ __forceinline__ uint32_t rotl32(uint32_t x, int r) { return (x << r) | (x >> (32 - r)); }
__device__ __forceinline__ float bits_to_gumbel(uint32_t b) {
    uint32_t fb = (b >> 9) | 0x3f800000u;
    float f = __uint_as_float(fb) - 1.0f;
    float u = (f > 0.f) ? f : 1.17549435e-38f;
    return -logf(-logf(u));
}
__global__ void gumbel_k() {
    int i = blockIdx.x * blockDim.x + threadIdx.x;
    if (i >= TT*NN*NA) return;
    const uint32_t ks0 = 0u, ks1 = 42u, ks2 = ks0 ^ ks1 ^ 0x1BD11BDAu;
    uint32_t x0 = 0u + ks0, x1 = (uint32_t)i + ks1;
#define RG4(a,b,c,d) \
    x0 += x1; x1 = rotl32(x1,a); x1 ^= x0; \
    x0 += x1; x1 = rotl32(x1,b); x1 ^= x0; \
    x0 += x1; x1 = rotl32(x1,c); x1 ^= x0; \
    x0 += x1; x1 = rotl32(x1,d); x1 ^= x0;
    RG4(13,15,26,6)  x0 += ks1; x1 += ks2 + 1u;
    RG4(17,29,16,24) x0 += ks2; x1 += ks0 + 2u;
    RG4(13,15,26,6)  x0 += ks0; x1 += ks1 + 3u;
    RG4(17,29,16,24) x0 += ks1; x1 += ks2 + 4u;
    RG4(13,15,26,6)  x0 += ks2; x1 += ks0 + 5u;
#undef RG4
    g_gum[i] = bits_to_gumbel(x0 ^ x1);
}

// ---------------------------------------------------------------- heads + pack
__global__ void __launch_bounds__(64)
pack_k(const float* __restrict__ H0, const float* __restrict__ H1,
       const int* __restrict__ actions, const int* __restrict__ p0,
       const float* __restrict__ loc, const float* __restrict__ scale,
       const float* __restrict__ crw, const float* __restrict__ crb,
       const float* __restrict__ aw, const float* __restrict__ ab,
       float* __restrict__ out, int has_tail) {
    int bx = blockIdx.x;
    int t = bx >> 8, n = bx & 255;
    int tid = threadIdx.x;
    __shared__ float h1s[128];
    __shared__ float hd[17];
    const float* h1g = H1 + ((size_t)t * NN + n) * HH;
    h1s[tid] = h1g[tid]; h1s[tid + 64] = h1g[tid + 64];
    __syncthreads();
    if (tid < 17) {
        const float* w = (tid == 0) ? crw : (aw + (size_t)(tid - 1) * HH);
        float b = (tid == 0) ? crb[0] : ab[tid - 1];
        float d0 = 0, d1 = 0, d2 = 0, d3 = 0;
#pragma unroll
        for (int k = 0; k < HH; k += 4) {
            d0 = fmaf(w[k],   h1s[k],   d0); d1 = fmaf(w[k+1], h1s[k+1], d1);
            d2 = fmaf(w[k+2], h1s[k+2], d2); d3 = fmaf(w[k+3], h1s[k+3], d3);
        }
        hd[tid] = b + ((d0 + d1) + (d2 + d3));
    }
    __syncthreads();
    float* row  = out + ((size_t)t * NN + n) * TOTP;
    float* row2 = out + ((size_t)TT * NN + n) * TOTP;
    bool tail = has_tail && (t == TT - 1);
    if (tid == 0) {
        const float* lg = hd + 1;
        float m = lg[0];
#pragma unroll
        for (int a = 1; a < NA; a++) m = fmaxf(m, lg[a]);
        float ex[NA], es = 0.f;
#pragma unroll
        for (int a = 0; a < NA; a++) { ex[a] = expf(lg[a] - m); es += ex[a]; }
        float inv = 1.f / es;
        const float* gm = g_gum + ((size_t)t * NN + n) * NA;
        int best = 0; float bb = lg[0] + gm[0];
#pragma unroll
        for (int a = 1; a < NA; a++) {
            float v = lg[a] + gm[a];
            if (v > bb) { bb = v; best = a; }
        }
        int at = actions[t * NN + n];
        float av = (float)((at < 0) ? best : at);
        row[0] = av;
#pragma unroll
        for (int a = 0; a < NA; a++) row[1 + a] = ex[a] * inv;
        row[17] = loc[n]; row[18] = scale[n]; row[19] = hd[0];
        row[276] = (float)(p0[n] + t + 1);
        if (tail) {
            row2[0] = av;
            for (int a = 0; a < NA; a++) row2[1 + a] = ex[a] * inv;
            row2[17] = loc[n]; row2[18] = scale[n]; row2[19] = hd[0];
            row2[276] = row[276];
        }
    }
    const float* h0g = H0 + ((size_t)t * NN + n) * HH;
#pragma unroll
    for (int q = 0; q < 2; q++) {
        int j = tid + q * 64;
        float v0 = h0g[j], v1 = h1s[j];
        row[20 + j] = v0; row[148 + j] = v1;
        if (tail) { row2[20 + j] = v0; row2[148 + j] = v1; }
    }
}

// ---------------------------------------------------------------- launch
extern "C" void kernel_launch(void* const* d_in, const int* in_sizes, int n_in,
                              void* d_out, int out_size) {
    const float* obs    = (const float*)d_in[0];
    const int*   acts   = (const int*)d_in[1];
    const int*   p0     = (const int*)d_in[2];
    const float* h0     = (const float*)d_in[3];
    const float* loc    = (const float*)d_in[4];
    const float* scl    = (const float*)d_in[5];
    const float* conv_w = (const float*)d_in[6];
    const float* conv_b = (const float*)d_in[7];
    const float* g0wih  = (const float*)d_in[8];
    const float* g0whh  = (const float*)d_in[9];
    const float* g0bih  = (const float*)d_in[10];
    const float* g0bhh  = (const float*)d_in[11];
    const float* g1wih  = (const float*)d_in[12];
    const float* g1whh  = (const float*)d_in[13];
    const float* g1bih  = (const float*)d_in[14];
    const float* g1bhh  = (const float*)d_in[15];
    const float* crw    = (const float*)d_in[16];
    const float* crb    = (const float*)d_in[17];
    const float* aw     = (const float*)d_in[18];
    const float* ab     = (const float*)d_in[19];
    float* out = (float*)d_out;

    float *pX, *pGi, *pG, *pH1;
    cudaGetSymbolAddress((void**)&pX, g_X);
    cudaGetSymbolAddress((void**)&pGi, g_gi);
    cudaGetSymbolAddress((void**)&pG, g_G);
    cudaGetSymbolAddress((void**)&pH1, g_H1);

    const int GEMM_SMEM = 2 * 128 * GP * 4;                 // 135,168 B
    const int REC_SMEM  = (384*36 + 256 + 768 + 256) * 4;   // 60,416 B
    cudaFuncSetAttribute(gemm4_k, cudaFuncAttributeMaxDynamicSharedMemorySize, GEMM_SMEM);
    cudaFuncSetAttribute(recur2_k, cudaFuncAttributeMaxDynamicSharedMemorySize, REC_SMEM);

    int has_tail = (out_size >= TT*NN*TOTP + NN*TOTP) ? 1 : 0;

    // phase 1: conv over obs[0]
    conv_k<<<4096, 256>>>(obs, conv_w, conv_b);
    // phase 2: gru0 layer 0
    gemm4_k<<<dim3(LL*NN/128, 3), 256, GEMM_SMEM>>>(pX, g0wih, g0bih, pGi);
    recur2_k<<<NN/2, 384, REC_SMEM>>>(pGi, g0whh, g0bhh, nullptr, pX, LL);
    // phase 2: gru0 layer 1
    gemm4_k<<<dim3(LL*NN/128, 3), 256, GEMM_SMEM>>>(pX, g0wih + G3*HH, g0bih + G3, pGi);
    recur2_k<<<NN/2, 384, REC_SMEM>>>(pGi, g0whh + G3*HH, g0bhh + G3, nullptr, pX, LL);
    // phase 3 prep
    gather_k<<<dim3(TT, NN), HH>>>(p0);
    gumbel_k<<<512, 256>>>();
    // phase 3: layer 0
    gemm4_k<<<dim3(TT*NN/128, 3), 256, GEMM_SMEM>>>(pG, g1wih, g1bih, pGi);
    recur2_k<<<NN/2, 384, REC_SMEM>>>(pGi, g1whh, g1bhh, h0, pG, TT);          // H0 series -> g_G
    // phase 3: layer 1
    gemm4_k<<<dim3(TT*NN/128, 3), 256, GEMM_SMEM>>>(pG, g1wih + G3*HH, g1bih + G3, pGi);
    recur2_k<<<NN/2, 384, REC_SMEM>>>(pGi, g1whh + G3*HH, g1bhh + G3, h0 + NN*HH, pH1, TT);
    // heads + pack
    pack_k<<<TT*NN, 64>>>(pG, pH1, acts, p0, loc, scl, crw, crb, aw, ab, out, has_tail);
}

// round 8
// speedup vs baseline: 1.1722x; 1.1128x over previous
#include <cuda_runtime.h>
#include <math.h>
#include <stdint.h>

#define TT 32
#define NN 256
#define LL 512
#define HH 128
#define G3 384
#define NA 16
#define TOTP 277
#define XP 130   // float2 pitch for duplicated X tile (gemm)
#define WP 132   // float pitch for W tile (gemm)

typedef unsigned long long u64;

__device__ __forceinline__ u64 ff2(u64 a, u64 b, u64 c) {
    u64 d;
    asm("fma.rn.f32x2 %0, %1, %2, %3;" : "=l"(d) : "l"(a), "l"(b), "l"(c));
    return d;
}
__device__ __forceinline__ float2 unpack(u64 v) {
    float2 r;
    asm("mov.b64 {%0,%1}, %2;" : "=f"(r.x), "=f"(r.y) : "l"(v));
    return r;
}

__device__ float g_X[LL*NN*HH];     // conv out / layer outputs
__device__ float g_gi[LL*NN*G3];    // precomputed input-gates
__device__ float g_G[TT*NN*HH];     // gathered rows, then H0 series
__device__ float g_H1[TT*NN*HH];    // H1 series
__device__ float g_gum[TT*NN*NA];   // gumbel noise

// ---------------------------------------------------------------- conv
__global__ void conv_k(const float* __restrict__ obs, const float* __restrict__ cw,
                       const float* __restrict__ cb) {
    int l = blockIdx.x, n = blockIdx.y, h = threadIdx.x;
    __shared__ float xs[9];
    if (h < 9) { int p = l - 4 + h; xs[h] = (p >= 0 && p < LL) ? obs[n*LL + p] : 0.f; }
    __syncthreads();
    float acc = cb[h];
#pragma unroll
    for (int k = 0; k < 9; k++) acc = fmaf(xs[k], cw[h*9 + k], acc);
    g_X[(l*NN + n)*HH + h] = fmaxf(acc, 0.f);
}

// ------------------------------------------------ GEMM: C[r][g] = bias[g] + X[r]·W[g]
// X [R,128] row-major, W [384,128] row-major, C [R,384]. 128x128 tile, 256 thr,
// 8x8 micro-tile, f32x2 packed FMA with duplicated-X smem tile (R5 version).
__global__ void __launch_bounds__(256, 1)
gemm2_k(const float* __restrict__ X, const float* __restrict__ W,
        const float* __restrict__ bias, float* __restrict__ C) {
    extern __shared__ float sm[];
    float2* Xs = (float2*)sm;              // [128][XP] duplicated (x,x)
    float*  Ws = sm + 2*128*XP;            // [128][WP]
    int tid = threadIdx.x;
    int r0 = blockIdx.x * 128, g0 = blockIdx.y * 128;
#pragma unroll
    for (int it = 0; it < 16; it++) {
        int idx = it * 256 + tid;
        int r = idx >> 5, kq = (idx & 31) * 4;
        float4 v = *(const float4*)&X[(size_t)(r0 + r) * HH + kq];
        Xs[(kq+0)*XP + r] = make_float2(v.x, v.x);
        Xs[(kq+1)*XP + r] = make_float2(v.y, v.y);
        Xs[(kq+2)*XP + r] = make_float2(v.z, v.z);
        Xs[(kq+3)*XP + r] = make_float2(v.w, v.w);
    }
#pragma unroll
    for (int it = 0; it < 16; it++) {
        int idx = it * 256 + tid;
        int g = idx & 127, kq = (idx >> 7) * 4;
        float4 w = *(const float4*)&W[(size_t)(g0 + g) * HH + kq];
        Ws[(kq+0)*WP + g] = w.x;
        Ws[(kq+1)*WP + g] = w.y;
        Ws[(kq+2)*WP + g] = w.z;
        Ws[(kq+3)*WP + g] = w.w;
    }
    __syncthreads();
    int tx = tid & 15, ty = tid >> 4;
    u64 acc[8][4];
#pragma unroll
    for (int i = 0; i < 8; i++)
#pragma unroll
        for (int j = 0; j < 4; j++) acc[i][j] = 0ULL;
#pragma unroll 4
    for (int k = 0; k < 128; k++) {
        const float2* xk = Xs + k * XP;
        const float*  wk = Ws + k * WP;
        ulonglong2 a01 = *(const ulonglong2*)(xk + ty*4);
        ulonglong2 a23 = *(const ulonglong2*)(xk + ty*4 + 2);
        ulonglong2 a45 = *(const ulonglong2*)(xk + ty*4 + 64);
        ulonglong2 a67 = *(const ulonglong2*)(xk + ty*4 + 66);
        ulonglong2 b03 = *(const ulonglong2*)(wk + tx*4);
        ulonglong2 b47 = *(const ulonglong2*)(wk + tx*4 + 64);
        u64 av[8] = {a01.x, a01.y, a23.x, a23.y, a45.x, a45.y, a67.x, a67.y};
        u64 bv[4] = {b03.x, b03.y, b47.x, b47.y};
#pragma unroll
        for (int i = 0; i < 8; i++)
#pragma unroll
            for (int j = 0; j < 4; j++)
                acc[i][j] = ff2(av[i], bv[j], acc[i][j]);
    }
    float4 bA = *(const float4*)&bias[g0 + tx*4];
    float4 bB = *(const float4*)&bias[g0 + tx*4 + 64];
#pragma unroll
    for (int i = 0; i < 8; i++) {
        int r = r0 + ty*4 + (i & 3) + (i >> 2) * 64;
        float2 q0 = unpack(acc[i][0]), q1 = unpack(acc[i][1]);
        float2 q2 = unpack(acc[i][2]), q3 = unpack(acc[i][3]);
        float4 o0 = make_float4(q0.x + bA.x, q0.y + bA.y, q1.x + bA.z, q1.y + bA.w);
        float4 o1 = make_float4(q2.x + bB.x, q2.y + bB.y, q3.x + bB.z, q3.y + bB.w);
        *(float4*)&C[(size_t)r * G3 + g0 + tx*4]      = o0;
        *(float4*)&C[(size_t)r * G3 + g0 + tx*4 + 64] = o1;
    }
}

// ---------------------------------------------- GRU recurrence, one layer, k-split
// 128 CTAs x 2 samples, 768 threads: thread (g, kh) does k-half kh of gate-row g
// for both samples. W: 48 k in regs + 16 k in smem. Partials combined via smem.
__global__ void __launch_bounds__(768, 1)
recur3_k(const float* __restrict__ gi, const float* __restrict__ whh,
         const float* __restrict__ bhh, const float* __restrict__ h0i,
         float* __restrict__ out, int steps) {
    extern __shared__ float sm[];
    float* Wsm = sm;                 // [768][20] smem W: 16 floats/thread, pitch 20
    float* h_s = Wsm + 768*20;       // [2][128]
    float* su0 = h_s + 256;          // [2][384] kh=0 partials (incl gi + bhh)
    float* su1 = su0 + 768;          // [2][384] kh=1 partials
    float* gin = su1 + 768;          // [2][128]
    int tid = threadIdx.x;
    int kh = (tid >= 384) ? 1 : 0;
    int g  = tid - kh * 384;
    int n0 = blockIdx.x * 2;
    const float* wrow = whh + (size_t)g * HH + kh * 64;
    u64 wr[24];
#pragma unroll
    for (int i = 0; i < 12; i++) {
        ulonglong2 t2 = *(const ulonglong2*)(wrow + 4*i);
        wr[2*i] = t2.x; wr[2*i+1] = t2.y;
    }
#pragma unroll
    for (int j = 0; j < 4; j++)
        *(float4*)&Wsm[tid*20 + 4*j] = *(const float4*)(wrow + 48 + 4*j);
    float bv = (kh == 0) ? bhh[g] : 0.f;
    if (tid < 256) {
        int s = tid >> 7, j = tid & 127;
        h_s[tid] = h0i ? h0i[(size_t)(n0 + s) * HH + j] : 0.f;
    }
    __syncthreads();
    const ulonglong2* hA = (const ulonglong2*)h_s + kh * 16;          // this k-half, sample 0
    const ulonglong2* hB = (const ulonglong2*)(h_s + HH) + kh * 16;   // sample 1
    const ulonglong2* wsp = (const ulonglong2*)&Wsm[tid*20];
    float gia = 0.f, gib = 0.f;
    if (kh == 0) {
        gia = gi[n0 * G3 + g];
        gib = gi[(n0 + 1) * G3 + g];
    }
    for (int t = 0; t < steps; t++) {
        u64 a0a = 0, a0b = 0, a1a = 0, a1b = 0;
#pragma unroll
        for (int i = 0; i < 12; i++) {
            ulonglong2 ha = hA[i], hb = hB[i];
            a0a = ff2(wr[2*i],   ha.x, a0a);
            a0b = ff2(wr[2*i+1], ha.y, a0b);
            a1a = ff2(wr[2*i],   hb.x, a1a);
            a1b = ff2(wr[2*i+1], hb.y, a1b);
        }
#pragma unroll
        for (int j = 0; j < 4; j++) {
            ulonglong2 ww = wsp[j];
            ulonglong2 ha = hA[12+j], hb = hB[12+j];
            a0a = ff2(ww.x, ha.x, a0a);
            a0b = ff2(ww.y, ha.y, a0b);
            a1a = ff2(ww.x, hb.x, a1a);
            a1b = ff2(ww.y, hb.y, a1b);
        }
        float2 q0a = unpack(a0a), q0b = unpack(a0b);
        float2 q1a = unpack(a1a), q1b = unpack(a1b);
        float p0 = bv + ((q0a.x + q0a.y) + (q0b.x + q0b.y));
        float p1 = bv + ((q1a.x + q1a.y) + (q1b.x + q1b.y));
        if (kh == 0) {
            if (g < 256) { p0 += gia; p1 += gib; }
            else { gin[g - 256] = gia; gin[128 + g - 256] = gib; }
            su0[g] = p0; su0[384 + g] = p1;
            // prefetch next-step gi (hidden under gate phase + syncs + next dot)
            if (t + 1 < steps) {
                const float* gp = gi + (size_t)(t + 1) * NN * G3;
                gia = gp[n0 * G3 + g];
                gib = gp[(n0 + 1) * G3 + g];
            }
        } else {
            su1[g] = p0; su1[384 + g] = p1;
        }
        __syncthreads();
        if (tid < 256) {
            int s = tid >> 7, j = tid & 127;
            const float* s0 = su0 + s * 384;
            const float* s1 = su1 + s * 384;
            float xr = s0[j] + s1[j];
            float xz = s0[128 + j] + s1[128 + j];
            float xn = s0[256 + j] + s1[256 + j];
            float r = __fdividef(1.f, 1.f + __expf(-xr));
            float z = __fdividef(1.f, 1.f + __expf(-xz));
            float y = fmaf(r, xn, gin[s * 128 + j]);
            float e = __expf(-2.f * fabsf(y));
            float th = __fdividef(1.f - e, 1.f + e);
            th = (y < 0.f) ? -th : th;
            float hn = (1.f - z) * th + z * h_s[tid];
            h_s[tid] = hn;
            out[((size_t)t * NN + n0 + s) * HH + j] = hn;
        }
        __syncthreads();
    }
}

// ---------------------------------------------------------------- gather M[n, p0+t]
__global__ void gather_k(const int* __restrict__ p0) {
    int t = blockIdx.x, n = blockIdx.y, h = threadIdx.x;
    int p = p0[n] + t;
    g_G[((size_t)t * NN + n) * HH + h] = g_X[((size_t)p * NN + n) * HH + h];
}

// ---------------------------------------------------------------- threefry gumbel
// JAX partitionable threefry: bits[i] = o0 ^ o1, counter (0, i), key (0, 42).
__device__ __forceinline__ uint32_t rotl32(uint32_t x, int r) { return (x << r) | (x >> (32 - r)); }
__device__ __forceinline__ float bits_to_gumbel(uint32_t b) {
    uint32_t fb = (b >> 9) | 0x3f800000u;
    float f = __uint_as_float(fb) - 1.0f;
    float u = (f > 0.f) ? f : 1.17549435e-38f;
    return -logf(-logf(u));
}
__global__ void gumbel_k() {
    int i = blockIdx.x * blockDim.x + threadIdx.x;
    if (i >= TT*NN*NA) return;
    const uint32_t ks0 = 0u, ks1 = 42u, ks2 = ks0 ^ ks1 ^ 0x1BD11BDAu;
    uint32_t x0 = 0u + ks0, x1 = (uint32_t)i + ks1;
#define RG4(a,b,c,d) \
    x0 += x1; x1 = rotl32(x1,a); x1 ^= x0; \
    x0 += x1; x1 = rotl32(x1,b); x1 ^= x0; \
    x0 += x1; x1 = rotl32(x1,c); x1 ^= x0; \
    x0 += x1; x1 = rotl32(x1,d); x1 ^= x0;
    RG4(13,15,26,6)  x0 += ks1; x1 += ks2 + 1u;
    RG4(17,29,16,24) x0 += ks2; x1 += ks0 + 2u;
    RG4(13,15,26,6)  x0 += ks0; x1 += ks1 + 3u;
    RG4(17,29,16,24) x0 += ks1; x1 += ks2 + 4u;
    RG4(13,15,26,6)  x0 += ks2; x1 += ks0 + 5u;
#undef RG4
    g_gum[i] = bits_to_gumbel(x0 ^ x1);
}

// ---------------------------------------------------------------- heads + pack
__global__ void __launch_bounds__(64)
pack_k(const float* __restrict__ H0, const float* __restrict__ H1,
       const int* __restrict__ actions, const int* __restrict__ p0,
       const float* __restrict__ loc, const float* __restrict__ scale,
       const float* __restrict__ crw, const float* __restrict__ crb,
       const float* __restrict__ aw, const float* __restrict__ ab,
       float* __restrict__ out, int has_tail) {
    int bx = blockIdx.x;
    int t = bx >> 8, n = bx & 255;
    int tid = threadIdx.x;
    __shared__ float h1s[128];
    __shared__ float hd[17];
    const float* h1g = H1 + ((size_t)t * NN + n) * HH;
    h1s[tid] = h1g[tid]; h1s[tid + 64] = h1g[tid + 64];
    __syncthreads();
    if (tid < 17) {
        const float* w = (tid == 0) ? crw : (aw + (size_t)(tid - 1) * HH);
        float b = (tid == 0) ? crb[0] : ab[tid - 1];
        float d0 = 0, d1 = 0, d2 = 0, d3 = 0;
#pragma unroll
        for (int k = 0; k < HH; k += 4) {
            d0 = fmaf(w[k],   h1s[k],   d0); d1 = fmaf(w[k+1], h1s[k+1], d1);
            d2 = fmaf(w[k+2], h1s[k+2], d2); d3 = fmaf(w[k+3], h1s[k+3], d3);
        }
        hd[tid] = b + ((d0 + d1) + (d2 + d3));
    }
    __syncthreads();
    float* row  = out + ((size_t)t * NN + n) * TOTP;
    float* row2 = out + ((size_t)TT * NN + n) * TOTP;
    bool tail = has_tail && (t == TT - 1);
    if (tid == 0) {
        const float* lg = hd + 1;
        float m = lg[0];
#pragma unroll
        for (int a = 1; a < NA; a++) m = fmaxf(m, lg[a]);
        float ex[NA], es = 0.f;
#pragma unroll
        for (int a = 0; a < NA; a++) { ex[a] = expf(lg[a] - m); es += ex[a]; }
        float inv = 1.f / es;
        const float* gm = g_gum + ((size_t)t * NN + n) * NA;
        int best = 0; float bb = lg[0] + gm[0];
#pragma unroll
        for (int a = 1; a < NA; a++) {
            float v = lg[a] + gm[a];
            if (v > bb) { bb = v; best = a; }
        }
        int at = actions[t * NN + n];
        float av = (float)((at < 0) ? best : at);
        row[0] = av;
#pragma unroll
        for (int a = 0; a < NA; a++) row[1 + a] = ex[a] * inv;
        row[17] = loc[n]; row[18] = scale[n]; row[19] = hd[0];
        row[276] = (float)(p0[n] + t + 1);
        if (tail) {
            row2[0] = av;
            for (int a = 0; a < NA; a++) row2[1 + a] = ex[a] * inv;
            row2[17] = loc[n]; row2[18] = scale[n]; row2[19] = hd[0];
            row2[276] = row[276];
        }
    }
    const float* h0g = H0 + ((size_t)t * NN + n) * HH;
#pragma unroll
    for (int q = 0; q < 2; q++) {
        int j = tid + q * 64;
        float v0 = h0g[j], v1 = h1s[j];
        row[20 + j] = v0; row[148 + j] = v1;
        if (tail) { row2[20 + j] = v0; row2[148 + j] = v1; }
    }
}

// ---------------------------------------------------------------- launch
extern "C" void kernel_launch(void* const* d_in, const int* in_sizes, int n_in,
                              void* d_out, int out_size) {
    const float* obs    = (const float*)d_in[0];
    const int*   acts   = (const int*)d_in[1];
    const int*   p0     = (const int*)d_in[2];
    const float* h0     = (const float*)d_in[3];
    const float* loc    = (const float*)d_in[4];
    const float* scl    = (const float*)d_in[5];
    const float* conv_w = (const float*)d_in[6];
    const float* conv_b = (const float*)d_in[7];
    const float* g0wih  = (const float*)d_in[8];
    const float* g0whh  = (const float*)d_in[9];
    const float* g0bih  = (const float*)d_in[10];
    const float* g0bhh  = (const float*)d_in[11];
    const float* g1wih  = (const float*)d_in[12];
    const float* g1whh  = (const float*)d_in[13];
    const float* g1bih  = (const float*)d_in[14];
    const float* g1bhh  = (const float*)d_in[15];
    const float* crw    = (const float*)d_in[16];
    const float* crb    = (const float*)d_in[17];
    const float* aw     = (const float*)d_in[18];
    const float* ab     = (const float*)d_in[19];
    float* out = (float*)d_out;

    float *pX, *pGi, *pG, *pH1;
    cudaGetSymbolAddress((void**)&pX, g_X);
    cudaGetSymbolAddress((void**)&pGi, g_gi);
    cudaGetSymbolAddress((void**)&pG, g_G);
    cudaGetSymbolAddress((void**)&pH1, g_H1);

    const int GEMM_SMEM = (2*128*XP + 128*WP) * 4;                   // 200,704 B
    const int REC_SMEM  = (768*20 + 256 + 768 + 768 + 256) * 4;      // 69,632 B
    cudaFuncSetAttribute(gemm2_k, cudaFuncAttributeMaxDynamicSharedMemorySize, GEMM_SMEM);
    cudaFuncSetAttribute(recur3_k, cudaFuncAttributeMaxDynamicSharedMemorySize, REC_SMEM);

    int has_tail = (out_size >= TT*NN*TOTP + NN*TOTP) ? 1 : 0;

    // phase 1: conv over obs[0]
    conv_k<<<dim3(LL, NN), HH>>>(obs, conv_w, conv_b);
    // phase 2: gru0 layer 0
    gemm2_k<<<dim3(LL*NN/128, 3), 256, GEMM_SMEM>>>(pX, g0wih, g0bih, pGi);
    recur3_k<<<NN/2, 768, REC_SMEM>>>(pGi, g0whh, g0bhh, nullptr, pX, LL);
    // phase 2: gru0 layer 1
    gemm2_k<<<dim3(LL*NN/128, 3), 256, GEMM_SMEM>>>(pX, g0wih + G3*HH, g0bih + G3, pGi);
    recur3_k<<<NN/2, 768, REC_SMEM>>>(pGi, g0whh + G3*HH, g0bhh + G3, nullptr, pX, LL);
    // phase 3 prep
    gather_k<<<dim3(TT, NN), HH>>>(p0);
    gumbel_k<<<512, 256>>>();
    // phase 3: layer 0
    gemm2_k<<<dim3(TT*NN/128, 3), 256, GEMM_SMEM>>>(pG, g1wih, g1bih, pGi);
    recur3_k<<<NN/2, 768, REC_SMEM>>>(pGi, g1whh, g1bhh, h0, pG, TT);          // H0 series -> g_G
    // phase 3: layer 1
    gemm2_k<<<dim3(TT*NN/128, 3), 256, GEMM_SMEM>>>(pG, g1wih + G3*HH, g1bih + G3, pGi);
    recur3_k<<<NN/2, 768, REC_SMEM>>>(pGi, g1whh + G3*HH, g1bhh + G3, h0 + NN*HH, pH1, TT);
    // heads + pack
    pack_k<<<TT*NN, 64>>>(pG, pH1, acts, p0, loc, scl, crw, crb, aw, ab, out, has_tail);
}

// round 10
// speedup vs baseline: 1.1754x; 1.0027x over previous
#include <cuda_runtime.h>
#include <math.h>
#include <stdint.h>

#define TT 32
#define NN 256
#define LL 512
#define HH 128
#define G3 384
#define NA 16
#define TOTP 277
#define TP 192   // skewed tile pitch (words per k-row)

typedef unsigned long long u64;

__device__ __forceinline__ u64 ff2(u64 a, u64 b, u64 c) {
    u64 d;
    asm("fma.rn.f32x2 %0, %1, %2, %3;" : "=l"(d) : "l"(a), "l"(b), "l"(c));
    return d;
}
__device__ __forceinline__ u64 dup2(float a) {
    u64 d;
    asm("mov.b64 %0, {%1, %1};" : "=l"(d) : "f"(a));
    return d;
}
__device__ __forceinline__ float2 unpack(u64 v) {
    float2 r;
    asm("mov.b64 {%0,%1}, %2;" : "=f"(r.x), "=f"(r.y) : "l"(v));
    return r;
}
// skew: insert 4 pad words every 8 cols -> lane stride 12 words -> 2-way banks max
__device__ __forceinline__ int phys(int c) { return c + ((c >> 3) << 2); }

__device__ float g_X[LL*NN*HH];     // conv out / layer outputs
__device__ float g_gi[LL*NN*G3];    // precomputed input-gates
__device__ float g_G[TT*NN*HH];     // gathered rows, then H0 series
__device__ float g_H1[TT*NN*HH];    // H1 series
__device__ float g_gum[TT*NN*NA];   // gumbel noise

// ---------------------------------------------------------------- conv
__global__ void conv_k(const float* __restrict__ obs, const float* __restrict__ cw,
                       const float* __restrict__ cb) {
    int l = blockIdx.x, n = blockIdx.y, h = threadIdx.x;
    __shared__ float xs[9];
    if (h < 9) { int p = l - 4 + h; xs[h] = (p >= 0 && p < LL) ? obs[n*LL + p] : 0.f; }
    __syncthreads();
    float acc = cb[h];
#pragma unroll
    for (int k = 0; k < 9; k++) acc = fmaf(xs[k], cw[h*9 + k], acc);
    g_X[(l*NN + n)*HH + h] = fmaxf(acc, 0.f);
}

// ------------------------------------------------ GEMM: C[r][g] = bias[g] + X[r]·W[g]
// 128x128 tile, 256 thr, 8x8 micro, k-split 2x64, skewed tiles (2-phase LDS),
// undup X + in-register dup. 2 CTAs/SM.
__global__ void __launch_bounds__(256, 2)
gemm7_k(const float* __restrict__ X, const float* __restrict__ W,
        const float* __restrict__ bias, float* __restrict__ C) {
    extern __shared__ float sm[];
    float* Xs = sm;            // [64][TP]
    float* Ws = sm + 64*TP;    // [64][TP]
    int tid = threadIdx.x;
    int r0 = blockIdx.x * 128, g0 = blockIdx.y * 128;
    int tx = tid & 15, ty = tid >> 4;
    u64 acc[8][4];
#pragma unroll
    for (int i = 0; i < 8; i++)
#pragma unroll
        for (int j = 0; j < 4; j++) acc[i][j] = 0ULL;

#pragma unroll
    for (int pass = 0; pass < 2; pass++) {
        int kb = pass * 64;
        // load 128 rows x 64 k of X and W (8 float4 each per thread)
#pragma unroll
        for (int it = 0; it < 8; it++) {
            int idx = it * 256 + tid;
            int r = idx >> 4, kq = (idx & 15) * 4;
            int pr = phys(r);
            float4 v = *(const float4*)&X[(size_t)(r0 + r) * HH + kb + kq];
            Xs[(kq+0)*TP + pr] = v.x; Xs[(kq+1)*TP + pr] = v.y;
            Xs[(kq+2)*TP + pr] = v.z; Xs[(kq+3)*TP + pr] = v.w;
            float4 w = *(const float4*)&W[(size_t)(g0 + r) * HH + kb + kq];
            Ws[(kq+0)*TP + pr] = w.x; Ws[(kq+1)*TP + pr] = w.y;
            Ws[(kq+2)*TP + pr] = w.z; Ws[(kq+3)*TP + pr] = w.w;
        }
        __syncthreads();
        int pa = phys(ty * 8), pb = phys(tx * 8);
#pragma unroll 8
        for (int k = 0; k < 64; k++) {
            const float* xk = Xs + k * TP + pa;
            const float* wk = Ws + k * TP + pb;
            float4 a03 = *(const float4*)(xk);
            float4 a47 = *(const float4*)(xk + 4);
            ulonglong2 b01 = *(const ulonglong2*)(wk);
            ulonglong2 b23 = *(const ulonglong2*)(wk + 4);
            u64 av[8];
            av[0] = dup2(a03.x); av[1] = dup2(a03.y);
            av[2] = dup2(a03.z); av[3] = dup2(a03.w);
            av[4] = dup2(a47.x); av[5] = dup2(a47.y);
            av[6] = dup2(a47.z); av[7] = dup2(a47.w);
            u64 bv[4] = {b01.x, b01.y, b23.x, b23.y};
#pragma unroll
            for (int i = 0; i < 8; i++)
#pragma unroll
                for (int j = 0; j < 4; j++)
                    acc[i][j] = ff2(av[i], bv[j], acc[i][j]);
        }
        __syncthreads();
    }
    float4 bA = *(const float4*)&bias[g0 + tx*8];
    float4 bB = *(const float4*)&bias[g0 + tx*8 + 4];
#pragma unroll
    for (int i = 0; i < 8; i++) {
        int r = r0 + ty*8 + i;
        float2 q0 = unpack(acc[i][0]), q1 = unpack(acc[i][1]);
        float2 q2 = unpack(acc[i][2]), q3 = unpack(acc[i][3]);
        float4 o0 = make_float4(q0.x + bA.x, q0.y + bA.y, q1.x + bA.z, q1.y + bA.w);
        float4 o1 = make_float4(q2.x + bB.x, q2.y + bB.y, q3.x + bB.z, q3.y + bB.w);
        *(float4*)&C[(size_t)r * G3 + g0 + tx*8]     = o0;
        *(float4*)&C[(size_t)r * G3 + g0 + tx*8 + 4] = o1;
    }
}

// ---------------------------------------------- GRU recurrence, one layer, k-split
// 128 CTAs x 2 samples, 768 threads: thread (g, kh) does k-half kh of gate-row g
// for both samples. W: 48 k in regs + 16 k in smem. Partials combined via smem.
__global__ void __launch_bounds__(768, 1)
recur3_k(const float* __restrict__ gi, const float* __restrict__ whh,
         const float* __restrict__ bhh, const float* __restrict__ h0i,
         float* __restrict__ out, int steps) {
    extern __shared__ float sm[];
    float* Wsm = sm;                 // [768][20] smem W: 16 floats/thread, pitch 20
    float* h_s = Wsm + 768*20;       // [2][128]
    float* su0 = h_s + 256;          // [2][384] kh=0 partials (incl gi + bhh)
    float* su1 = su0 + 768;          // [2][384] kh=1 partials
    float* gin = su1 + 768;          // [2][128]
    int tid = threadIdx.x;
    int kh = (tid >= 384) ? 1 : 0;
    int g  = tid - kh * 384;
    int n0 = blockIdx.x * 2;
    const float* wrow = whh + (size_t)g * HH + kh * 64;
    u64 wr[24];
#pragma unroll
    for (int i = 0; i < 12; i++) {
        ulonglong2 t2 = *(const ulonglong2*)(wrow + 4*i);
        wr[2*i] = t2.x; wr[2*i+1] = t2.y;
    }
#pragma unroll
    for (int j = 0; j < 4; j++)
        *(float4*)&Wsm[tid*20 + 4*j] = *(const float4*)(wrow + 48 + 4*j);
    float bv = (kh == 0) ? bhh[g] : 0.f;
    if (tid < 256) {
        int s = tid >> 7, j = tid & 127;
        h_s[tid] = h0i ? h0i[(size_t)(n0 + s) * HH + j] : 0.f;
    }
    __syncthreads();
    const ulonglong2* hA = (const ulonglong2*)h_s + kh * 16;          // this k-half, sample 0
    const ulonglong2* hB = (const ulonglong2*)(h_s + HH) + kh * 16;   // sample 1
    const ulonglong2* wsp = (const ulonglong2*)&Wsm[tid*20];
    float gia = 0.f, gib = 0.f;
    if (kh == 0) {
        gia = gi[n0 * G3 + g];
        gib = gi[(n0 + 1) * G3 + g];
    }
    for (int t = 0; t < steps; t++) {
        u64 a0a = 0, a0b = 0, a1a = 0, a1b = 0;
#pragma unroll
        for (int i = 0; i < 12; i++) {
            ulonglong2 ha = hA[i], hb = hB[i];
            a0a = ff2(wr[2*i],   ha.x, a0a);
            a0b = ff2(wr[2*i+1], ha.y, a0b);
            a1a = ff2(wr[2*i],   hb.x, a1a);
            a1b = ff2(wr[2*i+1], hb.y, a1b);
        }
#pragma unroll
        for (int j = 0; j < 4; j++) {
            ulonglong2 ww = wsp[j];
            ulonglong2 ha = hA[12+j], hb = hB[12+j];
            a0a = ff2(ww.x, ha.x, a0a);
            a0b = ff2(ww.y, ha.y, a0b);
            a1a = ff2(ww.x, hb.x, a1a);
            a1b = ff2(ww.y, hb.y, a1b);
        }
        float2 q0a = unpack(a0a), q0b = unpack(a0b);
        float2 q1a = unpack(a1a), q1b = unpack(a1b);
        float p0 = bv + ((q0a.x + q0a.y) + (q0b.x + q0b.y));
        float p1 = bv + ((q1a.x + q1a.y) + (q1b.x + q1b.y));
        if (kh == 0) {
            if (g < 256) { p0 += gia; p1 += gib; }
            else { gin[g - 256] = gia; gin[128 + g - 256] = gib; }
            su0[g] = p0; su0[384 + g] = p1;
            if (t + 1 < steps) {
                const float* gp = gi + (size_t)(t + 1) * NN * G3;
                gia = gp[n0 * G3 + g];
                gib = gp[(n0 + 1) * G3 + g];
            }
        } else {
            su1[g] = p0; su1[384 + g] = p1;
        }
        __syncthreads();
        if (tid < 256) {
            int s = tid >> 7, j = tid & 127;
            const float* s0 = su0 + s * 384;
            const float* s1 = su1 + s * 384;
            float xr = s0[j] + s1[j];
            float xz = s0[128 + j] + s1[128 + j];
            float xn = s0[256 + j] + s1[256 + j];
            float r = __fdividef(1.f, 1.f + __expf(-xr));
            float z = __fdividef(1.f, 1.f + __expf(-xz));
            float y = fmaf(r, xn, gin[s * 128 + j]);
            float e = __expf(-2.f * fabsf(y));
            float th = __fdividef(1.f - e, 1.f + e);
            th = (y < 0.f) ? -th : th;
            float hn = (1.f - z) * th + z * h_s[tid];
            h_s[tid] = hn;
            out[((size_t)t * NN + n0 + s) * HH + j] = hn;
        }
        __syncthreads();
    }
}

// ---------------------------------------------------------------- gather M[n, p0+t]
__global__ void gather_k(const int* __restrict__ p0) {
    int t = blockIdx.x, n = blockIdx.y, h = threadIdx.x;
    int p = p0[n] + t;
    g_G[((size_t)t * NN + n) * HH + h] = g_X[((size_t)p * NN + n) * HH + h];
}

// ---------------------------------------------------------------- threefry gumbel
// JAX partitionable threefry: bits[i] = o0 ^ o1, counter (0, i), key (0, 42).
__device__ __forceinline__ uint32_t rotl32(uint32_t x, int r) { return (x << r) | (x >> (32 - r)); }
__device__ __forceinline__ float bits_to_gumbel(uint32_t b) {
    uint32_t fb = (b >> 9) | 0x3f800000u;
    float f = __uint_as_float(fb) - 1.0f;
    float u = (f > 0.f) ? f : 1.17549435e-38f;
    return -logf(-logf(u));
}
__global__ void gumbel_k() {
    int i = blockIdx.x * blockDim.x + threadIdx.x;
    if (i >= TT*NN*NA) return;
    const uint32_t ks0 = 0u, ks1 = 42u, ks2 = ks0 ^ ks1 ^ 0x1BD11BDAu;
    uint32_t x0 = 0u + ks0, x1 = (uint32_t)i + ks1;
#define RG4(a,b,c,d) \
    x0 += x1; x1 = rotl32(x1,a); x1 ^= x0; \
    x0 += x1; x1 = rotl32(x1,b); x1 ^= x0; \
    x0 += x1; x1 = rotl32(x1,c); x1 ^= x0; \
    x0 += x1; x1 = rotl32(x1,d); x1 ^= x0;
    RG4(13,15,26,6)  x0 += ks1; x1 += ks2 + 1u;
    RG4(17,29,16,24) x0 += ks2; x1 += ks0 + 2u;
    RG4(13,15,26,6)  x0 += ks0; x1 += ks1 + 3u;
    RG4(17,29,16,24) x0 += ks1; x1 += ks2 + 4u;
    RG4(13,15,26,6)  x0 += ks2; x1 += ks0 + 5u;
#undef RG4
    g_gum[i] = bits_to_gumbel(x0 ^ x1);
}

// ---------------------------------------------------------------- heads + pack
__global__ void __launch_bounds__(64)
pack_k(const float* __restrict__ H0, const float* __restrict__ H1,
       const int* __restrict__ actions, const int* __restrict__ p0,
       const float* __restrict__ loc, const float* __restrict__ scale,
       const float* __restrict__ crw, const float* __restrict__ crb,
       const float* __restrict__ aw, const float* __restrict__ ab,
       float* __restrict__ out, int has_tail) {
    int bx = blockIdx.x;
    int t = bx >> 8, n = bx & 255;
    int tid = threadIdx.x;
    __shared__ float h1s[128];
    __shared__ float hd[17];
    const float* h1g = H1 + ((size_t)t * NN + n) * HH;
    h1s[tid] = h1g[tid]; h1s[tid + 64] = h1g[tid + 64];
    __syncthreads();
    if (tid < 17) {
        const float* w = (tid == 0) ? crw : (aw + (size_t)(tid - 1) * HH);
        float b = (tid == 0) ? crb[0] : ab[tid - 1];
        float d0 = 0, d1 = 0, d2 = 0, d3 = 0;
#pragma unroll
        for (int k = 0; k < HH; k += 4) {
            d0 = fmaf(w[k],   h1s[k],   d0); d1 = fmaf(w[k+1], h1s[k+1], d1);
            d2 = fmaf(w[k+2], h1s[k+2], d2); d3 = fmaf(w[k+3], h1s[k+3], d3);
        }
        hd[tid] = b + ((d0 + d1) + (d2 + d3));
    }
    __syncthreads();
    float* row  = out + ((size_t)t * NN + n) * TOTP;
    float* row2 = out + ((size_t)TT * NN + n) * TOTP;
    bool tail = has_tail && (t == TT - 1);
    if (tid == 0) {
        const float* lg = hd + 1;
        float m = lg[0];
#pragma unroll
        for (int a = 1; a < NA; a++) m = fmaxf(m, lg[a]);
        float ex[NA], es = 0.f;
#pragma unroll
        for (int a = 0; a < NA; a++) { ex[a] = expf(lg[a] - m); es += ex[a]; }
        float inv = 1.f / es;
        const float* gm = g_gum + ((size_t)t * NN + n) * NA;
        int best = 0; float bb = lg[0] + gm[0];
#pragma unroll
        for (int a = 1; a < NA; a++) {
            float v = lg[a] + gm[a];
            if (v > bb) { bb = v; best = a; }
        }
        int at = actions[t * NN + n];
        float av = (float)((at < 0) ? best : at);
        row[0] = av;
#pragma unroll
        for (int a = 0; a < NA; a++) row[1 + a] = ex[a] * inv;
        row[17] = loc[n]; row[18] = scale[n]; row[19] = hd[0];
        row[276] = (float)(p0[n] + t + 1);
        if (tail) {
            row2[0] = av;
            for (int a = 0; a < NA; a++) row2[1 + a] = ex[a] * inv;
            row2[17] = loc[n]; row2[18] = scale[n]; row2[19] = hd[0];
            row2[276] = row[276];
        }
    }
    const float* h0g = H0 + ((size_t)t * NN + n) * HH;
#pragma unroll
    for (int q = 0; q < 2; q++) {
        int j = tid + q * 64;
        float v0 = h0g[j], v1 = h1s[j];
        row[20 + j] = v0; row[148 + j] = v1;
        if (tail) { row2[20 + j] = v0; row2[148 + j] = v1; }
    }
}

// ---------------------------------------------------------------- launch
extern "C" void kernel_launch(void* const* d_in, const int* in_sizes, int n_in,
                              void* d_out, int out_size) {
    const float* obs    = (const float*)d_in[0];
    const int*   acts   = (const int*)d_in[1];
    const int*   p0     = (const int*)d_in[2];
    const float* h0     = (const float*)d_in[3];
    const float* loc    = (const float*)d_in[4];
    const float* scl    = (const float*)d_in[5];
    const float* conv_w = (const float*)d_in[6];
    const float* conv_b = (const float*)d_in[7];
    const float* g0wih  = (const float*)d_in[8];
    const float* g0whh  = (const float*)d_in[9];
    const float* g0bih  = (const float*)d_in[10];
    const float* g0bhh  = (const float*)d_in[11];
    const float* g1wih  = (const float*)d_in[12];
    const float* g1whh  = (const float*)d_in[13];
    const float* g1bih  = (const float*)d_in[14];
    const float* g1bhh  = (const float*)d_in[15];
    const float* crw    = (const float*)d_in[16];
    const float* crb    = (const float*)d_in[17];
    const float* aw     = (const float*)d_in[18];
    const float* ab     = (const float*)d_in[19];
    float* out = (float*)d_out;

    float *pX, *pGi, *pG, *pH1;
    cudaGetSymbolAddress((void**)&pX, g_X);
    cudaGetSymbolAddress((void**)&pGi, g_gi);
    cudaGetSymbolAddress((void**)&pG, g_G);
    cudaGetSymbolAddress((void**)&pH1, g_H1);

    const int GEMM_SMEM = 2 * 64 * TP * 4;                           // 98,304 B
    const int REC_SMEM  = (768*20 + 256 + 768 + 768 + 256) * 4;      // 69,632 B
    cudaFuncSetAttribute(gemm7_k, cudaFuncAttributeMaxDynamicSharedMemorySize, GEMM_SMEM);
    cudaFuncSetAttribute(recur3_k, cudaFuncAttributeMaxDynamicSharedMemorySize, REC_SMEM);

    int has_tail = (out_size >= TT*NN*TOTP + NN*TOTP) ? 1 : 0;

    // phase 1: conv over obs[0]
    conv_k<<<dim3(LL, NN), HH>>>(obs, conv_w, conv_b);
    // phase 2: gru0 layer 0
    gemm7_k<<<dim3(LL*NN/128, 3), 256, GEMM_SMEM>>>(pX, g0wih, g0bih, pGi);
    recur3_k<<<NN/2, 768, REC_SMEM>>>(pGi, g0whh, g0bhh, nullptr, pX, LL);
    // phase 2: gru0 layer 1
    gemm7_k<<<dim3(LL*NN/128, 3), 256, GEMM_SMEM>>>(pX, g0wih + G3*HH, g0bih + G3, pGi);
    recur3_k<<<NN/2, 768, REC_SMEM>>>(pGi, g0whh + G3*HH, g0bhh + G3, nullptr, pX, LL);
    // phase 3 prep
    gather_k<<<dim3(TT, NN), HH>>>(p0);
    gumbel_k<<<512, 256>>>();
    // phase 3: layer 0
    gemm7_k<<<dim3(TT*NN/128, 3), 256, GEMM_SMEM>>>(pG, g1wih, g1bih, pGi);
    recur3_k<<<NN/2, 768, REC_SMEM>>>(pGi, g1whh, g1bhh, h0, pG, TT);          // H0 series -> g_G
    // phase 3: layer 1
    gemm7_k<<<dim3(TT*NN/128, 3), 256, GEMM_SMEM>>>(pG, g1wih + G3*HH, g1bih + G3, pGi);
    recur3_k<<<NN/2, 768, REC_SMEM>>>(pGi, g1whh + G3*HH, g1bhh + G3, h0 + NN*HH, pH1, TT);
    // heads + pack
    pack_k<<<TT*NN, 64>>>(pG, pH1, acts, p0, loc, scl, crw, crb, aw, ab, out, has_tail);
}

// round 14
// speedup vs baseline: 1.4802x; 1.2593x over previous
#include <cuda_runtime.h>
#include <cuda_bf16.h>
#include <math.h>
#include <stdint.h>

#define TT 32
#define NN 256
#define LL 512
#define HH 128
#define G3 384
#define NA 16
#define TOTP 277
#define PK 136            // bf16 tile pitch (row stride 272B -> conflict-free ldmatrix)
#define TILE_B (128*PK*2) // 34816 bytes per bf16 tile

typedef unsigned long long u64;

__device__ __forceinline__ u64 ff2(u64 a, u64 b, u64 c) {
    u64 d;
    asm("fma.rn.f32x2 %0, %1, %2, %3;" : "=l"(d) : "l"(a), "l"(b), "l"(c));
    return d;
}
__device__ __forceinline__ float2 unpack(u64 v) {
    float2 r;
    asm("mov.b64 {%0,%1}, %2;" : "=f"(r.x), "=f"(r.y) : "l"(v));
    return r;
}
__device__ __forceinline__ uint32_t smem_u32(const void* p) {
    uint32_t a;
    asm("{ .reg .u64 t; cvta.to.shared.u64 t, %1; cvt.u32.u64 %0, t; }" : "=r"(a) : "l"(p));
    return a;
}

__device__ float g_X[LL*NN*HH];
__device__ float g_gi[LL*NN*G3];
__device__ float g_G[TT*NN*HH];
__device__ float g_H1[TT*NN*HH];
__device__ float g_gum[TT*NN*NA];

// ---------------------------------------------------------------- conv
__global__ void conv_k(const float* __restrict__ obs, const float* __restrict__ cw,
                       const float* __restrict__ cb) {
    int l = blockIdx.x, n = blockIdx.y, h = threadIdx.x;
    __shared__ float xs[9];
    if (h < 9) { int p = l - 4 + h; xs[h] = (p >= 0 && p < LL) ? obs[n*LL + p] : 0.f; }
    __syncthreads();
    float acc = cb[h];
#pragma unroll
    for (int k = 0; k < 9; k++) acc = fmaf(xs[k], cw[h*9 + k], acc);
    g_X[(l*NN + n)*HH + h] = fmaxf(acc, 0.f);
}

// ------------------------------------------------ split-bf16 HMMA GEMM
// C[r][g] = bias[g] + X[r]·W[g]; X [R,128], W [384,128] row-major.
// 128x128 CTA tile, 8 warps (4M x 2N, warp tile 32x64), mma.m16n8k16 bf16,
// 3 passes: Xh*Wh + Xh*Wl + Xl*Wh (lo*lo dropped, ~4e-5 rel).
__device__ __forceinline__ void split_store(char* hi, char* lo, int row, int col4, float4 v) {
    int off = row * (PK*2) + col4 * 2;
    __nv_bfloat16 h0 = __float2bfloat16(v.x), h1 = __float2bfloat16(v.y);
    __nv_bfloat16 h2 = __float2bfloat16(v.z), h3 = __float2bfloat16(v.w);
    __nv_bfloat16 l0 = __float2bfloat16(v.x - __bfloat162float(h0));
    __nv_bfloat16 l1 = __float2bfloat16(v.y - __bfloat162float(h1));
    __nv_bfloat16 l2 = __float2bfloat16(v.z - __bfloat162float(h2));
    __nv_bfloat16 l3 = __float2bfloat16(v.w - __bfloat162float(h3));
    uint2 hp, lp;
    hp.x = (uint32_t)__bfloat16_as_ushort(h0) | ((uint32_t)__bfloat16_as_ushort(h1) << 16);
    hp.y = (uint32_t)__bfloat16_as_ushort(h2) | ((uint32_t)__bfloat16_as_ushort(h3) << 16);
    lp.x = (uint32_t)__bfloat16_as_ushort(l0) | ((uint32_t)__bfloat16_as_ushort(l1) << 16);
    lp.y = (uint32_t)__bfloat16_as_ushort(l2) | ((uint32_t)__bfloat16_as_ushort(l3) << 16);
    *(uint2*)(hi + off) = hp;
    *(uint2*)(lo + off) = lp;
}

#define LDSM_X4(r0, r1, r2, r3, addr) \
    asm volatile("ldmatrix.sync.aligned.m8n8.x4.shared.b16 {%0,%1,%2,%3}, [%4];" \
        : "=r"(r0), "=r"(r1), "=r"(r2), "=r"(r3) : "r"(addr))

#define MMA_BF16(c, a0, a1, a2, a3, b0, b1) \
    asm volatile("mma.sync.aligned.m16n8k16.row.col.f32.bf16.bf16.f32 " \
        "{%0,%1,%2,%3}, {%4,%5,%6,%7}, {%8,%9}, {%0,%1,%2,%3};" \
        : "+f"((c)[0]), "+f"((c)[1]), "+f"((c)[2]), "+f"((c)[3]) \
        : "r"(a0), "r"(a1), "r"(a2), "r"(a3), "r"(b0), "r"(b1))

__global__ void __launch_bounds__(256, 1)
gemmbf_k(const float* __restrict__ X, const float* __restrict__ W,
         const float* __restrict__ bias, float* __restrict__ C) {
    extern __shared__ char smc[];
    char* Ah = smc;
    char* Al = smc + TILE_B;
    char* Bh = smc + 2*TILE_B;
    char* Bl = smc + 3*TILE_B;
    float* bs = (float*)(smc + 4*TILE_B);
    int tid = threadIdx.x, lane = tid & 31, wid = tid >> 5;
    int r0 = blockIdx.x * 128, g0 = blockIdx.y * 128;

    // load fp32 tiles, split to bf16 hi/lo
#pragma unroll
    for (int it = 0; it < 16; it++) {
        int idx = it * 256 + tid;
        int r = idx >> 5, kq = (idx & 31) * 4;
        split_store(Ah, Al, r, kq, *(const float4*)&X[(size_t)(r0 + r) * HH + kq]);
        split_store(Bh, Bl, r, kq, *(const float4*)&W[(size_t)(g0 + r) * HH + kq]);
    }
    if (tid < 128) bs[tid] = bias[g0 + tid];
    __syncthreads();

    int wm = wid & 3, wn = wid >> 2;   // 4 M-tiles x 2 N-tiles of warps
    float c[2][8][4];
#pragma unroll
    for (int mi = 0; mi < 2; mi++)
#pragma unroll
        for (int nj = 0; nj < 8; nj++)
#pragma unroll
            for (int q = 0; q < 4; q++) c[mi][nj][q] = 0.f;

    // per-lane ldmatrix byte offsets (within a tile)
    int aRow = 32*wm + (lane & 15);
    int aK   = (lane >> 4) * 8;
    uint32_t aoff0 = (uint32_t)((aRow       ) * PK + aK) * 2;
    uint32_t aoff1 = (uint32_t)((aRow + 16  ) * PK + aK) * 2;
    int bRow = 64*wn + ((lane >> 4) << 3) + (lane & 7);
    int bK   = ((lane >> 3) & 1) * 8;
    uint32_t boff[4];
#pragma unroll
    for (int p = 0; p < 4; p++)
        boff[p] = (uint32_t)((bRow + 16*p) * PK + bK) * 2;

    uint32_t aBase[3] = { smem_u32(Ah), smem_u32(Ah), smem_u32(Al) };
    uint32_t bBase[3] = { smem_u32(Bh), smem_u32(Bl), smem_u32(Bh) };

#pragma unroll
    for (int pass = 0; pass < 3; pass++) {
        uint32_t ab = aBase[pass], bb = bBase[pass];
#pragma unroll
        for (int ks = 0; ks < 8; ks++) {
            uint32_t kb = ks * 32;   // 16 bf16 = 32 bytes
            uint32_t a0[4], a1[4];
            LDSM_X4(a0[0], a0[1], a0[2], a0[3], ab + aoff0 + kb);
            LDSM_X4(a1[0], a1[1], a1[2], a1[3], ab + aoff1 + kb);
#pragma unroll
            for (int p = 0; p < 4; p++) {
                uint32_t b0, b1, b2, b3;
                LDSM_X4(b0, b1, b2, b3, bb + boff[p] + kb);
                MMA_BF16(c[0][2*p],   a0[0], a0[1], a0[2], a0[3], b0, b1);
                MMA_BF16(c[0][2*p+1], a0[0], a0[1], a0[2], a0[3], b2, b3);
                MMA_BF16(c[1][2*p],   a1[0], a1[1], a1[2], a1[3], b0, b1);
                MMA_BF16(c[1][2*p+1], a1[0], a1[1], a1[2], a1[3], b2, b3);
            }
        }
    }

    // epilogue: c0,c1 -> row grp, cols q*2,+1 ; c2,c3 -> row grp+8
    int grp = lane >> 2, qid = lane & 3;
#pragma unroll
    for (int mi = 0; mi < 2; mi++) {
        int r = r0 + 32*wm + 16*mi + grp;
#pragma unroll
        for (int nj = 0; nj < 8; nj++) {
            int col = 64*wn + 8*nj + qid*2;
            float b0 = bs[col], b1 = bs[col+1];
            float2 v0 = make_float2(c[mi][nj][0] + b0, c[mi][nj][1] + b1);
            float2 v1 = make_float2(c[mi][nj][2] + b0, c[mi][nj][3] + b1);
            *(float2*)&C[(size_t)r * G3 + g0 + col]       = v0;
            *(float2*)&C[(size_t)(r+8) * G3 + g0 + col]   = v1;
        }
    }
}

// ---------------------------------------------- GRU recurrence (k-split, 768 thr)
__global__ void __launch_bounds__(768, 1)
recur3_k(const float* __restrict__ gi, const float* __restrict__ whh,
         const float* __restrict__ bhh, const float* __restrict__ h0i,
         float* __restrict__ out, int steps) {
    extern __shared__ float sm[];
    float* Wsm = sm;
    float* h_s = Wsm + 768*20;
    float* su0 = h_s + 256;
    float* su1 = su0 + 768;
    float* gin = su1 + 768;
    int tid = threadIdx.x;
    int kh = (tid >= 384) ? 1 : 0;
    int g  = tid - kh * 384;
    int n0 = blockIdx.x * 2;
    const float* wrow = whh + (size_t)g * HH + kh * 64;
    u64 wr[24];
#pragma unroll
    for (int i = 0; i < 12; i++) {
        ulonglong2 t2 = *(const ulonglong2*)(wrow + 4*i);
        wr[2*i] = t2.x; wr[2*i+1] = t2.y;
    }
#pragma unroll
    for (int j = 0; j < 4; j++)
        *(float4*)&Wsm[tid*20 + 4*j] = *(const float4*)(wrow + 48 + 4*j);
    float bv = (kh == 0) ? bhh[g] : 0.f;
    if (tid < 256) {
        int s = tid >> 7, j = tid & 127;
        h_s[tid] = h0i ? h0i[(size_t)(n0 + s) * HH + j] : 0.f;
    }
    __syncthreads();
    const ulonglong2* hA = (const ulonglong2*)h_s + kh * 16;
    const ulonglong2* hB = (const ulonglong2*)(h_s + HH) + kh * 16;
    const ulonglong2* wsp = (const ulonglong2*)&Wsm[tid*20];
    float gia = 0.f, gib = 0.f;
    if (kh == 0) {
        gia = gi[n0 * G3 + g];
        gib = gi[(n0 + 1) * G3 + g];
    }
    for (int t = 0; t < steps; t++) {
        u64 a0a = 0, a0b = 0, a1a = 0, a1b = 0;
#pragma unroll
        for (int i = 0; i < 12; i++) {
            ulonglong2 ha = hA[i], hb = hB[i];
            a0a = ff2(wr[2*i],   ha.x, a0a);
            a0b = ff2(wr[2*i+1], ha.y, a0b);
            a1a = ff2(wr[2*i],   hb.x, a1a);
            a1b = ff2(wr[2*i+1], hb.y, a1b);
        }
#pragma unroll
        for (int j = 0; j < 4; j++) {
            ulonglong2 ww = wsp[j];
            ulonglong2 ha = hA[12+j], hb = hB[12+j];
            a0a = ff2(ww.x, ha.x, a0a);
            a0b = ff2(ww.y, ha.y, a0b);
            a1a = ff2(ww.x, hb.x, a1a);
            a1b = ff2(ww.y, hb.y, a1b);
        }
        float2 q0a = unpack(a0a), q0b = unpack(a0b);
        float2 q1a = unpack(a1a), q1b = unpack(a1b);
        float p0 = bv + ((q0a.x + q0a.y) + (q0b.x + q0b.y));
        float p1 = bv + ((q1a.x + q1a.y) + (q1b.x + q1b.y));
        if (kh == 0) {
            if (g < 256) { p0 += gia; p1 += gib; }
            else { gin[g - 256] = gia; gin[128 + g - 256] = gib; }
            su0[g] = p0; su0[384 + g] = p1;
            if (t + 1 < steps) {
                const float* gp = gi + (size_t)(t + 1) * NN * G3;
                gia = gp[n0 * G3 + g];
                gib = gp[(n0 + 1) * G3 + g];
            }
        } else {
            su1[g] = p0; su1[384 + g] = p1;
        }
        __syncthreads();
        if (tid < 256) {
            int s = tid >> 7, j = tid & 127;
            const float* s0 = su0 + s * 384;
            const float* s1 = su1 + s * 384;
            float xr = s0[j] + s1[j];
            float xz = s0[128 + j] + s1[128 + j];
            float xn = s0[256 + j] + s1[256 + j];
            float r = __fdividef(1.f, 1.f + __expf(-xr));
            float z = __fdividef(1.f, 1.f + __expf(-xz));
            float y = fmaf(r, xn, gin[s * 128 + j]);
            float e = __expf(-2.f * fabsf(y));
            float th = __fdividef(1.f - e, 1.f + e);
            th = (y < 0.f) ? -th : th;
            float hn = (1.f - z) * th + z * h_s[tid];
            h_s[tid] = hn;
            out[((size_t)t * NN + n0 + s) * HH + j] = hn;
        }
        __syncthreads();
    }
}

// ---------------------------------------------------------------- gather
__global__ void gather_k(const int* __restrict__ p0) {
    int t = blockIdx.x, n = blockIdx.y, h = threadIdx.x;
    int p = p0[n] + t;
    g_G[((size_t)t * NN + n) * HH + h] = g_X[((size_t)p * NN + n) * HH + h];
}

// ---------------------------------------------------------------- gumbel
__device__ __forceinline__ uint32_t rotl32(uint32_t x, int r) { return (x << r) | (x >> (32 - r)); }
__device__ __forceinline__ float bits_to_gumbel(uint32_t b) {
    uint32_t fb = (b >> 9) | 0x3f800000u;
    float f = __uint_as_float(fb) - 1.0f;
    float u = (f > 0.f) ? f : 1.17549435e-38f;
    return -logf(-logf(u));
}
__global__ void gumbel_k() {
    int i = blockIdx.x * blockDim.x + threadIdx.x;
    if (i >= TT*NN*NA) return;
    const uint32_t ks0 = 0u, ks1 = 42u, ks2 = ks0 ^ ks1 ^ 0x1BD11BDAu;
    uint32_t x0 = 0u + ks0, x1 = (uint32_t)i + ks1;
#define RG4(a,b,c,d) \
    x0 += x1; x1 = rotl32(x1,a); x1 ^= x0; \
    x0 += x1; x1 = rotl32(x1,b); x1 ^= x0; \
    x0 += x1; x1 = rotl32(x1,c); x1 ^= x0; \
    x0 += x1; x1 = rotl32(x1,d); x1 ^= x0;
    RG4(13,15,26,6)  x0 += ks1; x1 += ks2 + 1u;
    RG4(17,29,16,24) x0 += ks2; x1 += ks0 + 2u;
    RG4(13,15,26,6)  x0 += ks0; x1 += ks1 + 3u;
    RG4(17,29,16,24) x0 += ks1; x1 += ks2 + 4u;
    RG4(13,15,26,6)  x0 += ks2; x1 += ks0 + 5u;
#undef RG4
    g_gum[i] = bits_to_gumbel(x0 ^ x1);
}

// ---------------------------------------------------------------- heads + pack
__global__ void __launch_bounds__(64)
pack_k(const float* __restrict__ H0, const float* __restrict__ H1,
       const int* __restrict__ actions, const int* __restrict__ p0,
       const float* __restrict__ loc, const float* __restrict__ scale,
       const float* __restrict__ crw, const float* __restrict__ crb,
       const float* __restrict__ aw, const float* __restrict__ ab,
       float* __restrict__ out, int has_tail) {
    int bx = blockIdx.x;
    int t = bx >> 8, n = bx & 255;
    int tid = threadIdx.x;
    __shared__ float h1s[128];
    __shared__ float hd[17];
    const float* h1g = H1 + ((size_t)t * NN + n) * HH;
    h1s[tid] = h1g[tid]; h1s[tid + 64] = h1g[tid + 64];
    __syncthreads();
    if (tid < 17) {
        const float* w = (tid == 0) ? crw : (aw + (size_t)(tid - 1) * HH);
        float b = (tid == 0) ? crb[0] : ab[tid - 1];
        float d0 = 0, d1 = 0, d2 = 0, d3 = 0;
#pragma unroll
        for (int k = 0; k < HH; k += 4) {
            d0 = fmaf(w[k],   h1s[k],   d0); d1 = fmaf(w[k+1], h1s[k+1], d1);
            d2 = fmaf(w[k+2], h1s[k+2], d2); d3 = fmaf(w[k+3], h1s[k+3], d3);
        }
        hd[tid] = b + ((d0 + d1) + (d2 + d3));
    }
    __syncthreads();
    float* row  = out + ((size_t)t * NN + n) * TOTP;
    float* row2 = out + ((size_t)TT * NN + n) * TOTP;
    bool tail = has_tail && (t == TT - 1);
    if (tid == 0) {
        const float* lg = hd + 1;
        float m = lg[0];
#pragma unroll
        for (int a = 1; a < NA; a++) m = fmaxf(m, lg[a]);
        float ex[NA], es = 0.f;
#pragma unroll
        for (int a = 0; a < NA; a++) { ex[a] = expf(lg[a] - m); es += ex[a]; }
        float inv = 1.f / es;
        const float* gm = g_gum + ((size_t)t * NN + n) * NA;
        int best = 0; float bb = lg[0] + gm[0];
#pragma unroll
        for (int a = 1; a < NA; a++) {
            float v = lg[a] + gm[a];
            if (v > bb) { bb = v; best = a; }
        }
        int at = actions[t * NN + n];
        float av = (float)((at < 0) ? best : at);
        row[0] = av;
#pragma unroll
        for (int a = 0; a < NA; a++) row[1 + a] = ex[a] * inv;
        row[17] = loc[n]; row[18] = scale[n]; row[19] = hd[0];
        row[276] = (float)(p0[n] + t + 1);
        if (tail) {
            row2[0] = av;
            for (int a = 0; a < NA; a++) row2[1 + a] = ex[a] * inv;
            row2[17] = loc[n]; row2[18] = scale[n]; row2[19] = hd[0];
            row2[276] = row[276];
        }
    }
    const float* h0g = H0 + ((size_t)t * NN + n) * HH;
#pragma unroll
    for (int q = 0; q < 2; q++) {
        int j = tid + q * 64;
        float v0 = h0g[j], v1 = h1s[j];
        row[20 + j] = v0; row[148 + j] = v1;
        if (tail) { row2[20 + j] = v0; row2[148 + j] = v1; }
    }
}

// ---------------------------------------------------------------- launch
extern "C" void kernel_launch(void* const* d_in, const int* in_sizes, int n_in,
                              void* d_out, int out_size) {
    const float* obs    = (const float*)d_in[0];
    const int*   acts   = (const int*)d_in[1];
    const int*   p0     = (const int*)d_in[2];
    const float* h0     = (const float*)d_in[3];
    const float* loc    = (const float*)d_in[4];
    const float* scl    = (const float*)d_in[5];
    const float* conv_w = (const float*)d_in[6];
    const float* conv_b = (const float*)d_in[7];
    const float* g0wih  = (const float*)d_in[8];
    const float* g0whh  = (const float*)d_in[9];
    const float* g0bih  = (const float*)d_in[10];
    const float* g0bhh  = (const float*)d_in[11];
    const float* g1wih  = (const float*)d_in[12];
    const float* g1whh  = (const float*)d_in[13];
    const float* g1bih  = (const float*)d_in[14];
    const float* g1bhh  = (const float*)d_in[15];
    const float* crw    = (const float*)d_in[16];
    const float* crb    = (const float*)d_in[17];
    const float* aw     = (const float*)d_in[18];
    const float* ab     = (const float*)d_in[19];
    float* out = (float*)d_out;

    float *pX, *pGi, *pG, *pH1;
    cudaGetSymbolAddress((void**)&pX, g_X);
    cudaGetSymbolAddress((void**)&pGi, g_gi);
    cudaGetSymbolAddress((void**)&pG, g_G);
    cudaGetSymbolAddress((void**)&pH1, g_H1);

    const int GEMM_SMEM = 4 * TILE_B + 512;                          // 139,776 B
    const int REC_SMEM  = (768*20 + 256 + 768 + 768 + 256) * 4;      // 69,632 B
    cudaFuncSetAttribute(gemmbf_k, cudaFuncAttributeMaxDynamicSharedMemorySize, GEMM_SMEM);
    cudaFuncSetAttribute(recur3_k, cudaFuncAttributeMaxDynamicSharedMemorySize, REC_SMEM);

    int has_tail = (out_size >= TT*NN*TOTP + NN*TOTP) ? 1 : 0;

    // phase 1: conv over obs[0]
    conv_k<<<dim3(LL, NN), HH>>>(obs, conv_w, conv_b);
    // phase 2: gru0 layer 0
    gemmbf_k<<<dim3(LL*NN/128, 3), 256, GEMM_SMEM>>>(pX, g0wih, g0bih, pGi);
    recur3_k<<<NN/2, 768, REC_SMEM>>>(pGi, g0whh, g0bhh, nullptr, pX, LL);
    // phase 2: gru0 layer 1
    gemmbf_k<<<dim3(LL*NN/128, 3), 256, GEMM_SMEM>>>(pX, g0wih + G3*HH, g0bih + G3, pGi);
    recur3_k<<<NN/2, 768, REC_SMEM>>>(pGi, g0whh + G3*HH, g0bhh + G3, nullptr, pX, LL);
    // phase 3 prep
    gather_k<<<dim3(TT, NN), HH>>>(p0);
    gumbel_k<<<512, 256>>>();
    // phase 3: layer 0
    gemmbf_k<<<dim3(TT*NN/128, 3), 256, GEMM_SMEM>>>(pG, g1wih, g1bih, pGi);
    recur3_k<<<NN/2, 768, REC_SMEM>>>(pGi, g1whh, g1bhh, h0, pG, TT);
    // phase 3: layer 1
    gemmbf_k<<<dim3(TT*NN/128, 3), 256, GEMM_SMEM>>>(pG, g1wih + G3*HH, g1bih + G3, pGi);
    recur3_k<<<NN/2, 768, REC_SMEM>>>(pGi, g1whh + G3*HH, g1bhh + G3, h0 + NN*HH, pH1, TT);
    // heads + pack
    pack_k<<<TT*NN, 64>>>(pG, pH1, acts, p0, loc, scl, crw, crb, aw, ab, out, has_tail);
}

// round 16
// speedup vs baseline: 1.4832x; 1.0021x over previous
#include <cuda_runtime.h>
#include <cuda_bf16.h>
#include <math.h>
#include <stdint.h>

#define TT 32
#define NN 256
#define LL 512
#define HH 128
#define G3 384
#define NA 16
#define TOTP 277
#define PK 136            // bf16 tile pitch (row stride 272B -> conflict-free ldmatrix)
#define TILE_B (128*PK*2) // 34816 bytes per bf16 tile

typedef unsigned long long u64;

__device__ __forceinline__ u64 ff2(u64 a, u64 b, u64 c) {
    u64 d;
    asm("fma.rn.f32x2 %0, %1, %2, %3;" : "=l"(d) : "l"(a), "l"(b), "l"(c));
    return d;
}
__device__ __forceinline__ float2 unpack(u64 v) {
    float2 r;
    asm("mov.b64 {%0,%1}, %2;" : "=f"(r.x), "=f"(r.y) : "l"(v));
    return r;
}
__device__ __forceinline__ uint32_t smem_u32(const void* p) {
    uint32_t a;
    asm("{ .reg .u64 t; cvta.to.shared.u64 t, %1; cvt.u32.u64 %0, t; }" : "=r"(a) : "l"(p));
    return a;
}

// ---------------- MUFU-free activations ----------------
// reciprocal: magic-constant seed + 3 Newton iterations (FMA only, ~1e-8 rel)
__device__ __forceinline__ float fast_recip(float q) {
    float r = __uint_as_float(0x7EF311C3u - __float_as_uint(q));
    r = r * (2.0f - q * r);
    r = r * (2.0f - q * r);
    r = r * (2.0f - q * r);
    return r;
}
// Eigen-style float tanh: odd deg-13 / even deg-6 rational, clamp +-7.9053 (~2 ulp)
__device__ __forceinline__ float fast_tanh(float x) {
    const float CL = 7.90531110763549805f;
    x = fminf(fmaxf(x, -CL), CL);
    float x2 = x * x;
    float p = -2.76076847742355e-16f;
    p = fmaf(p, x2, 2.00018790482477e-13f);
    p = fmaf(p, x2, -8.60467152213735e-11f);
    p = fmaf(p, x2, 5.12229709037114e-08f);
    p = fmaf(p, x2, 1.48572235717979e-05f);
    p = fmaf(p, x2, 6.37261928875436e-04f);
    p = fmaf(p, x2, 4.89352455891786e-03f);
    p = p * x;
    float q = 1.19825839466702e-06f;
    q = fmaf(q, x2, 1.18534705686654e-04f);
    q = fmaf(q, x2, 2.26843463243900e-03f);
    q = fmaf(q, x2, 4.89352518554385e-03f);
    return p * fast_recip(q);
}
__device__ __forceinline__ float fast_sigmoid(float x) {
    return fmaf(0.5f, fast_tanh(0.5f * x), 0.5f);
}

__device__ float g_X[LL*NN*HH];
__device__ float g_gi[LL*NN*G3];
__device__ float g_G[TT*NN*HH];
__device__ float g_H1[TT*NN*HH];
__device__ float g_gum[TT*NN*NA];

// ---------------------------------------------------------------- conv
__global__ void conv_k(const float* __restrict__ obs, const float* __restrict__ cw,
                       const float* __restrict__ cb) {
    int l = blockIdx.x, n = blockIdx.y, h = threadIdx.x;
    __shared__ float xs[9];
    if (h < 9) { int p = l - 4 + h; xs[h] = (p >= 0 && p < LL) ? obs[n*LL + p] : 0.f; }
    __syncthreads();
    float acc = cb[h];
#pragma unroll
    for (int k = 0; k < 9; k++) acc = fmaf(xs[k], cw[h*9 + k], acc);
    g_X[(l*NN + n)*HH + h] = fmaxf(acc, 0.f);
}

// ------------------------------------------------ split-bf16 HMMA GEMM
__device__ __forceinline__ void split_store(char* hi, char* lo, int row, int col4, float4 v) {
    int off = row * (PK*2) + col4 * 2;
    __nv_bfloat16 h0 = __float2bfloat16(v.x), h1 = __float2bfloat16(v.y);
    __nv_bfloat16 h2 = __float2bfloat16(v.z), h3 = __float2bfloat16(v.w);
    __nv_bfloat16 l0 = __float2bfloat16(v.x - __bfloat162float(h0));
    __nv_bfloat16 l1 = __float2bfloat16(v.y - __bfloat162float(h1));
    __nv_bfloat16 l2 = __float2bfloat16(v.z - __bfloat162float(h2));
    __nv_bfloat16 l3 = __float2bfloat16(v.w - __bfloat162float(h3));
    uint2 hp, lp;
    hp.x = (uint32_t)__bfloat16_as_ushort(h0) | ((uint32_t)__bfloat16_as_ushort(h1) << 16);
    hp.y = (uint32_t)__bfloat16_as_ushort(h2) | ((uint32_t)__bfloat16_as_ushort(h3) << 16);
    lp.x = (uint32_t)__bfloat16_as_ushort(l0) | ((uint32_t)__bfloat16_as_ushort(l1) << 16);
    lp.y = (uint32_t)__bfloat16_as_ushort(l2) | ((uint32_t)__bfloat16_as_ushort(l3) << 16);
    *(uint2*)(hi + off) = hp;
    *(uint2*)(lo + off) = lp;
}

#define LDSM_X4(r0, r1, r2, r3, addr) \
    asm volatile("ldmatrix.sync.aligned.m8n8.x4.shared.b16 {%0,%1,%2,%3}, [%4];" \
        : "=r"(r0), "=r"(r1), "=r"(r2), "=r"(r3) : "r"(addr))

#define MMA_BF16(c, a0, a1, a2, a3, b0, b1) \
    asm volatile("mma.sync.aligned.m16n8k16.row.col.f32.bf16.bf16.f32 " \
        "{%0,%1,%2,%3}, {%4,%5,%6,%7}, {%8,%9}, {%0,%1,%2,%3};" \
        : "+f"((c)[0]), "+f"((c)[1]), "+f"((c)[2]), "+f"((c)[3]) \
        : "r"(a0), "r"(a1), "r"(a2), "r"(a3), "r"(b0), "r"(b1))

__global__ void __launch_bounds__(256, 1)
gemmbf_k(const float* __restrict__ X, const float* __restrict__ W,
         const float* __restrict__ bias, float* __restrict__ C) {
    extern __shared__ char smc[];
    char* Ah = smc;
    char* Al = smc + TILE_B;
    char* Bh = smc + 2*TILE_B;
    char* Bl = smc + 3*TILE_B;
    float* bs = (float*)(smc + 4*TILE_B);
    int tid = threadIdx.x, lane = tid & 31, wid = tid >> 5;
    int r0 = blockIdx.x * 128, g0 = blockIdx.y * 128;

#pragma unroll
    for (int it = 0; it < 16; it++) {
        int idx = it * 256 + tid;
        int r = idx >> 5, kq = (idx & 31) * 4;
        split_store(Ah, Al, r, kq, *(const float4*)&X[(size_t)(r0 + r) * HH + kq]);
        split_store(Bh, Bl, r, kq, *(const float4*)&W[(size_t)(g0 + r) * HH + kq]);
    }
    if (tid < 128) bs[tid] = bias[g0 + tid];
    __syncthreads();

    int wm = wid & 3, wn = wid >> 2;
    float c[2][8][4];
#pragma unroll
    for (int mi = 0; mi < 2; mi++)
#pragma unroll
        for (int nj = 0; nj < 8; nj++)
#pragma unroll
            for (int q = 0; q < 4; q++) c[mi][nj][q] = 0.f;

    int aRow = 32*wm + (lane & 15);
    int aK   = (lane >> 4) * 8;
    uint32_t aoff0 = (uint32_t)((aRow       ) * PK + aK) * 2;
    uint32_t aoff1 = (uint32_t)((aRow + 16  ) * PK + aK) * 2;
    int bRow = 64*wn + ((lane >> 4) << 3) + (lane & 7);
    int bK   = ((lane >> 3) & 1) * 8;
    uint32_t boff[4];
#pragma unroll
    for (int p = 0; p < 4; p++)
        boff[p] = (uint32_t)((bRow + 16*p) * PK + bK) * 2;

    uint32_t aBase[3] = { smem_u32(Ah), smem_u32(Ah), smem_u32(Al) };
    uint32_t bBase[3] = { smem_u32(Bh), smem_u32(Bl), smem_u32(Bh) };

#pragma unroll
    for (int pass = 0; pass < 3; pass++) {
        uint32_t ab = aBase[pass], bb = bBase[pass];
#pragma unroll
        for (int ks = 0; ks < 8; ks++) {
            uint32_t kb = ks * 32;
            uint32_t a0[4], a1[4];
            LDSM_X4(a0[0], a0[1], a0[2], a0[3], ab + aoff0 + kb);
            LDSM_X4(a1[0], a1[1], a1[2], a1[3], ab + aoff1 + kb);
#pragma unroll
            for (int p = 0; p < 4; p++) {
                uint32_t b0, b1, b2, b3;
                LDSM_X4(b0, b1, b2, b3, bb + boff[p] + kb);
                MMA_BF16(c[0][2*p],   a0[0], a0[1], a0[2], a0[3], b0, b1);
                MMA_BF16(c[0][2*p+1], a0[0], a0[1], a0[2], a0[3], b2, b3);
                MMA_BF16(c[1][2*p],   a1[0], a1[1], a1[2], a1[3], b0, b1);
                MMA_BF16(c[1][2*p+1], a1[0], a1[1], a1[2], a1[3], b2, b3);
            }
        }
    }

    int grp = lane >> 2, qid = lane & 3;
#pragma unroll
    for (int mi = 0; mi < 2; mi++) {
        int r = r0 + 32*wm + 16*mi + grp;
#pragma unroll
        for (int nj = 0; nj < 8; nj++) {
            int col = 64*wn + 8*nj + qid*2;
            float b0 = bs[col], b1 = bs[col+1];
            float2 v0 = make_float2(c[mi][nj][0] + b0, c[mi][nj][1] + b1);
            float2 v1 = make_float2(c[mi][nj][2] + b0, c[mi][nj][3] + b1);
            *(float2*)&C[(size_t)r * G3 + g0 + col]       = v0;
            *(float2*)&C[(size_t)(r+8) * G3 + g0 + col]   = v1;
        }
    }
}

// ---------------------------------------------- GRU recurrence (k-split, 768 thr)
// MUFU-free gate phase (rational tanh + Newton reciprocal).
__global__ void __launch_bounds__(768, 1)
recur3_k(const float* __restrict__ gi, const float* __restrict__ whh,
         const float* __restrict__ bhh, const float* __restrict__ h0i,
         float* __restrict__ out, int steps) {
    extern __shared__ float sm[];
    float* Wsm = sm;
    float* h_s = Wsm + 768*20;
    float* su0 = h_s + 256;
    float* su1 = su0 + 768;
    float* gin = su1 + 768;
    int tid = threadIdx.x;
    int kh = (tid >= 384) ? 1 : 0;
    int g  = tid - kh * 384;
    int n0 = blockIdx.x * 2;
    const float* wrow = whh + (size_t)g * HH + kh * 64;
    u64 wr[24];
#pragma unroll
    for (int i = 0; i < 12; i++) {
        ulonglong2 t2 = *(const ulonglong2*)(wrow + 4*i);
        wr[2*i] = t2.x; wr[2*i+1] = t2.y;
    }
#pragma unroll
    for (int j = 0; j < 4; j++)
        *(float4*)&Wsm[tid*20 + 4*j] = *(const float4*)(wrow + 48 + 4*j);
    float bv = (kh == 0) ? bhh[g] : 0.f;
    if (tid < 256) {
        int s = tid >> 7, j = tid & 127;
        h_s[tid] = h0i ? h0i[(size_t)(n0 + s) * HH + j] : 0.f;
    }
    __syncthreads();
    const ulonglong2* hA = (const ulonglong2*)h_s + kh * 16;
    const ulonglong2* hB = (const ulonglong2*)(h_s + HH) + kh * 16;
    const ulonglong2* wsp = (const ulonglong2*)&Wsm[tid*20];
    float gia = 0.f, gib = 0.f;
    if (kh == 0) {
        gia = gi[n0 * G3 + g];
        gib = gi[(n0 + 1) * G3 + g];
    }
    for (int t = 0; t < steps; t++) {
        u64 a0a = 0, a0b = 0, a1a = 0, a1b = 0;
#pragma unroll
        for (int i = 0; i < 12; i++) {
            ulonglong2 ha = hA[i], hb = hB[i];
            a0a = ff2(wr[2*i],   ha.x, a0a);
            a0b = ff2(wr[2*i+1], ha.y, a0b);
            a1a = ff2(wr[2*i],   hb.x, a1a);
            a1b = ff2(wr[2*i+1], hb.y, a1b);
        }
#pragma unroll
        for (int j = 0; j < 4; j++) {
            ulonglong2 ww = wsp[j];
            ulonglong2 ha = hA[12+j], hb = hB[12+j];
            a0a = ff2(ww.x, ha.x, a0a);
            a0b = ff2(ww.y, ha.y, a0b);
            a1a = ff2(ww.x, hb.x, a1a);
            a1b = ff2(ww.y, hb.y, a1b);
        }
        float2 q0a = unpack(a0a), q0b = unpack(a0b);
        float2 q1a = unpack(a1a), q1b = unpack(a1b);
        float p0 = bv + ((q0a.x + q0a.y) + (q0b.x + q0b.y));
        float p1 = bv + ((q1a.x + q1a.y) + (q1b.x + q1b.y));
        if (kh == 0) {
            if (g < 256) { p0 += gia; p1 += gib; }
            else { gin[g - 256] = gia; gin[128 + g - 256] = gib; }
            su0[g] = p0; su0[384 + g] = p1;
            if (t + 1 < steps) {
                const float* gp = gi + (size_t)(t + 1) * NN * G3;
                gia = gp[n0 * G3 + g];
                gib = gp[(n0 + 1) * G3 + g];
            }
        } else {
            su1[g] = p0; su1[384 + g] = p1;
        }
        __syncthreads();
        if (tid < 256) {
            int s = tid >> 7, j = tid & 127;
            const float* s0 = su0 + s * 384;
            const float* s1 = su1 + s * 384;
            float xr = s0[j] + s1[j];
            float xz = s0[128 + j] + s1[128 + j];
            float xn = s0[256 + j] + s1[256 + j];
            float r = fast_sigmoid(xr);
            float z = fast_sigmoid(xz);
            float y = fmaf(r, xn, gin[s * 128 + j]);
            float th = fast_tanh(y);
            float hn = (1.f - z) * th + z * h_s[tid];
            h_s[tid] = hn;
            out[((size_t)t * NN + n0 + s) * HH + j] = hn;
        }
        __syncthreads();
    }
}

// ---------------------------------------------------------------- gather
__global__ void gather_k(const int* __restrict__ p0) {
    int t = blockIdx.x, n = blockIdx.y, h = threadIdx.x;
    int p = p0[n] + t;
    g_G[((size_t)t * NN + n) * HH + h] = g_X[((size_t)p * NN + n) * HH + h];
}

// ---------------------------------------------------------------- gumbel
__device__ __forceinline__ uint32_t rotl32(uint32_t x, int r) { return (x << r) | (x >> (32 - r)); }
__device__ __forceinline__ float bits_to_gumbel(uint32_t b) {
    uint32_t fb = (b >> 9) | 0x3f800000u;
    float f = __uint_as_float(fb) - 1.0f;
    float u = (f > 0.f) ? f : 1.17549435e-38f;
    return -logf(-logf(u));
}
__global__ void gumbel_k() {
    int i = blockIdx.x * blockDim.x + threadIdx.x;
    if (i >= TT*NN*NA) return;
    const uint32_t ks0 = 0u, ks1 = 42u, ks2 = ks0 ^ ks1 ^ 0x1BD11BDAu;
    uint32_t x0 = 0u + ks0, x1 = (uint32_t)i + ks1;
#define RG4(a,b,c,d) \
    x0 += x1; x1 = rotl32(x1,a); x1 ^= x0; \
    x0 += x1; x1 = rotl32(x1,b); x1 ^= x0; \
    x0 += x1; x1 = rotl32(x1,c); x1 ^= x0; \
    x0 += x1; x1 = rotl32(x1,d); x1 ^= x0;
    RG4(13,15,26,6)  x0 += ks1; x1 += ks2 + 1u;
    RG4(17,29,16,24) x0 += ks2; x1 += ks0 + 2u;
    RG4(13,15,26,6)  x0 += ks0; x1 += ks1 + 3u;
    RG4(17,29,16,24) x0 += ks1; x1 += ks2 + 4u;
    RG4(13,15,26,6)  x0 += ks2; x1 += ks0 + 5u;
#undef RG4
    g_gum[i] = bits_to_gumbel(x0 ^ x1);
}

// ---------------------------------------------------------------- heads + pack
__global__ void __launch_bounds__(64)
pack_k(const float* __restrict__ H0, const float* __restrict__ H1,
       const int* __restrict__ actions, const int* __restrict__ p0,
       const float* __restrict__ loc, const float* __restrict__ scale,
       const float* __restrict__ crw, const float* __restrict__ crb,
       const float* __restrict__ aw, const float* __restrict__ ab,
       float* __restrict__ out, int has_tail) {
    int bx = blockIdx.x;
    int t = bx >> 8, n = bx & 255;
    int tid = threadIdx.x;
    __shared__ float h1s[128];
    __shared__ float hd[17];
    const float* h1g = H1 + ((size_t)t * NN + n) * HH;
    h1s[tid] = h1g[tid]; h1s[tid + 64] = h1g[tid + 64];
    __syncthreads();
    if (tid < 17) {
        const float* w = (tid == 0) ? crw : (aw + (size_t)(tid - 1) * HH);
        float b = (tid == 0) ? crb[0] : ab[tid - 1];
        float d0 = 0, d1 = 0, d2 = 0, d3 = 0;
#pragma unroll
        for (int k = 0; k < HH; k += 4) {
            d0 = fmaf(w[k],   h1s[k],   d0); d1 = fmaf(w[k+1], h1s[k+1], d1);
            d2 = fmaf(w[k+2], h1s[k+2], d2); d3 = fmaf(w[k+3], h1s[k+3], d3);
        }
        hd[tid] = b + ((d0 + d1) + (d2 + d3));
    }
    __syncthreads();
    float* row  = out + ((size_t)t * NN + n) * TOTP;
    float* row2 = out + ((size_t)TT * NN + n) * TOTP;
    bool tail = has_tail && (t == TT - 1);
    if (tid == 0) {
        const float* lg = hd + 1;
        float m = lg[0];
#pragma unroll
        for (int a = 1; a < NA; a++) m = fmaxf(m, lg[a]);
        float ex[NA], es = 0.f;
#pragma unroll
        for (int a = 0; a < NA; a++) { ex[a] = expf(lg[a] - m); es += ex[a]; }
        float inv = 1.f / es;
        const float* gm = g_gum + ((size_t)t * NN + n) * NA;
        int best = 0; float bb = lg[0] + gm[0];
#pragma unroll
        for (int a = 1; a < NA; a++) {
            float v = lg[a] + gm[a];
            if (v > bb) { bb = v; best = a; }
        }
        int at = actions[t * NN + n];
        float av = (float)((at < 0) ? best : at);
        row[0] = av;
#pragma unroll
        for (int a = 0; a < NA; a++) row[1 + a] = ex[a] * inv;
        row[17] = loc[n]; row[18] = scale[n]; row[19] = hd[0];
        row[276] = (float)(p0[n] + t + 1);
        if (tail) {
            row2[0] = av;
            for (int a = 0; a < NA; a++) row2[1 + a] = ex[a] * inv;
            row2[17] = loc[n]; row2[18] = scale[n]; row2[19] = hd[0];
            row2[276] = row[276];
        }
    }
    const float* h0g = H0 + ((size_t)t * NN + n) * HH;
#pragma unroll
    for (int q = 0; q < 2; q++) {
        int j = tid + q * 64;
        float v0 = h0g[j], v1 = h1s[j];
        row[20 + j] = v0; row[148 + j] = v1;
        if (tail) { row2[20 + j] = v0; row2[148 + j] = v1; }
    }
}

// ---------------------------------------------------------------- launch
extern "C" void kernel_launch(void* const* d_in, const int* in_sizes, int n_in,
                              void* d_out, int out_size) {
    const float* obs    = (const float*)d_in[0];
    const int*   acts   = (const int*)d_in[1];
    const int*   p0     = (const int*)d_in[2];
    const float* h0     = (const float*)d_in[3];
    const float* loc    = (const float*)d_in[4];
    const float* scl    = (const float*)d_in[5];
    const float* conv_w = (const float*)d_in[6];
    const float* conv_b = (const float*)d_in[7];
    const float* g0wih  = (const float*)d_in[8];
    const float* g0whh  = (const float*)d_in[9];
    const float* g0bih  = (const float*)d_in[10];
    const float* g0bhh  = (const float*)d_in[11];
    const float* g1wih  = (const float*)d_in[12];
    const float* g1whh  = (const float*)d_in[13];
    const float* g1bih  = (const float*)d_in[14];
    const float* g1bhh  = (const float*)d_in[15];
    const float* crw    = (const float*)d_in[16];
    const float* crb    = (const float*)d_in[17];
    const float* aw     = (const float*)d_in[18];
    const float* ab     = (const float*)d_in[19];
    float* out = (float*)d_out;

    float *pX, *pGi, *pG, *pH1;
    cudaGetSymbolAddress((void**)&pX, g_X);
    cudaGetSymbolAddress((void**)&pGi, g_gi);
    cudaGetSymbolAddress((void**)&pG, g_G);
    cudaGetSymbolAddress((void**)&pH1, g_H1);

    const int GEMM_SMEM = 4 * TILE_B + 512;                          // 139,776 B
    const int REC_SMEM  = (768*20 + 256 + 768 + 768 + 256) * 4;      // 69,632 B
    cudaFuncSetAttribute(gemmbf_k, cudaFuncAttributeMaxDynamicSharedMemorySize, GEMM_SMEM);
    cudaFuncSetAttribute(recur3_k, cudaFuncAttributeMaxDynamicSharedMemorySize, REC_SMEM);

    int has_tail = (out_size >= TT*NN*TOTP + NN*TOTP) ? 1 : 0;

    // phase 1: conv over obs[0]
    conv_k<<<dim3(LL, NN), HH>>>(obs, conv_w, conv_b);
    // phase 2: gru0 layer 0
    gemmbf_k<<<dim3(LL*NN/128, 3), 256, GEMM_SMEM>>>(pX, g0wih, g0bih, pGi);
    recur3_k<<<NN/2, 768, REC_SMEM>>>(pGi, g0whh, g0bhh, nullptr, pX, LL);
    // phase 2: gru0 layer 1
    gemmbf_k<<<dim3(LL*NN/128, 3), 256, GEMM_SMEM>>>(pX, g0wih + G3*HH, g0bih + G3, pGi);
    recur3_k<<<NN/2, 768, REC_SMEM>>>(pGi, g0whh + G3*HH, g0bhh + G3, nullptr, pX, LL);
    // phase 3 prep
    gather_k<<<dim3(TT, NN), HH>>>(p0);
    gumbel_k<<<512, 256>>>();
    // phase 3: layer 0
    gemmbf_k<<<dim3(TT*NN/128, 3), 256, GEMM_SMEM>>>(pG, g1wih, g1bih, pGi);
    recur3_k<<<NN/2, 768, REC_SMEM>>>(pGi, g1whh, g1bhh, h0, pG, TT);
    // phase 3: layer 1
    gemmbf_k<<<dim3(TT*NN/128, 3), 256, GEMM_SMEM>>>(pG, g1wih + G3*HH, g1bih + G3, pGi);
    recur3_k<<<NN/2, 768, REC_SMEM>>>(pGi, g1whh + G3*HH, g1bhh + G3, h0 + NN*HH, pH1, TT);
    // heads + pack
    pack_k<<<TT*NN, 64>>>(pG, pH1, acts, p0, loc, scl, crw, crb, aw, ab, out, has_tail);
}